// round 9
// baseline (speedup 1.0000x reference)
#include <cuda_runtime.h>
#include <cuda_bf16.h>
#include <cstdint>

#define D 1024
#define NH 16
#define HD 64
#define U_LEN 2048
#define R_LEN 256
#define L_LEN 1024
#define M_LEN 512
#define QLEN 2304   // U + R
#define KVLEN 3840  // M + R + L + U
#define KVIN 2816   // M + R + U
#define MR 768      // M + R

#define KEY_OFF (QLEN * D)
#define VAL_OFF (KEY_OFF + KVLEN * D)

#define SCALE_LOG2E 0.1803368801111204f   // 0.125 * log2(e)

// ---------------- scratch (allocation-free rule: __device__ globals) --------
__device__ __nv_bfloat16 g_qin_hi[QLEN * D], g_qin_lo[QLEN * D];
__device__ __nv_bfloat16 g_kvin_hi[KVIN * D], g_kvin_lo[KVIN * D];
__device__ __nv_bfloat16 g_wq_hi[D * D], g_wq_lo[D * D];
__device__ __nv_bfloat16 g_wkv_hi[2 * D * D], g_wkv_lo[2 * D * D];
__device__ __nv_bfloat16 g_wo_hi[D * D], g_wo_lo[D * D];
__device__ __nv_bfloat16 g_q_hi[QLEN * D], g_q_lo[QLEN * D];   // q * 0.125*log2e
__device__ __nv_bfloat16 g_k_hi[KVLEN * D], g_k_lo[KVLEN * D];
__device__ __nv_bfloat16 g_v_hi[KVLEN * D], g_v_lo[KVLEN * D];
__device__ __nv_bfloat16 g_at_hi[QLEN * D], g_at_lo[QLEN * D];

// ---------------- helpers ---------------------------------------------------
static __device__ __forceinline__ uint32_t s2u(const void* p) {
    uint32_t a;
    asm("{ .reg .u64 t; cvta.to.shared.u64 t, %1; cvt.u32.u64 %0, t; }"
        : "=r"(a) : "l"(p));
    return a;
}

static __device__ __forceinline__ void ldmx4(uint32_t* r, uint32_t addr) {
    asm volatile("ldmatrix.sync.aligned.m8n8.x4.shared.b16 {%0,%1,%2,%3}, [%4];"
                 : "=r"(r[0]), "=r"(r[1]), "=r"(r[2]), "=r"(r[3]) : "r"(addr));
}
static __device__ __forceinline__ void ldmx4t(uint32_t* r, uint32_t addr) {
    asm volatile("ldmatrix.sync.aligned.m8n8.x4.trans.shared.b16 {%0,%1,%2,%3}, [%4];"
                 : "=r"(r[0]), "=r"(r[1]), "=r"(r[2]), "=r"(r[3]) : "r"(addr));
}

static __device__ __forceinline__ void mma_bf16(float* c, const uint32_t* a,
                                                uint32_t b0, uint32_t b1) {
    asm volatile("mma.sync.aligned.m16n8k16.row.col.f32.bf16.bf16.f32 "
                 "{%0,%1,%2,%3}, {%4,%5,%6,%7}, {%8,%9}, {%0,%1,%2,%3};"
                 : "+f"(c[0]), "+f"(c[1]), "+f"(c[2]), "+f"(c[3])
                 : "r"(a[0]), "r"(a[1]), "r"(a[2]), "r"(a[3]), "r"(b0), "r"(b1));
}

static __device__ __forceinline__ void cpa16(uint32_t s, const void* g) {
    asm volatile("cp.async.cg.shared.global [%0], [%1], 16;" :: "r"(s), "l"(g));
}
#define CP_COMMIT() asm volatile("cp.async.commit_group;" ::: "memory")
#define CP_WAIT1() asm volatile("cp.async.wait_group 1;" ::: "memory")
#define CP_WAIT0() asm volatile("cp.async.wait_group 0;" ::: "memory")

static __device__ __forceinline__ uint32_t pack2(__nv_bfloat16 a, __nv_bfloat16 b) {
    uint16_t ua = *(uint16_t*)&a, ub = *(uint16_t*)&b;
    return (uint32_t)ua | ((uint32_t)ub << 16);
}
static __device__ __forceinline__ void split2(float x, __nv_bfloat16& h, __nv_bfloat16& l) {
    h = __float2bfloat16(x);
    l = __float2bfloat16(x - __bfloat162float(h));
}

// ---------------- conversion kernels ----------------------------------------
__global__ void conv_split(const float* __restrict__ s, __nv_bfloat16* __restrict__ hi,
                           __nv_bfloat16* __restrict__ lo, int n4) {
    int i = blockIdx.x * blockDim.x + threadIdx.x;
    if (i >= n4) return;
    float4 v = ((const float4*)s)[i];
    __nv_bfloat16 h0, l0, h1, l1, h2, l2, h3, l3;
    split2(v.x, h0, l0); split2(v.y, h1, l1);
    split2(v.z, h2, l2); split2(v.w, h3, l3);
    ((uint32_t*)hi)[2 * i] = pack2(h0, h1);
    ((uint32_t*)hi)[2 * i + 1] = pack2(h2, h3);
    ((uint32_t*)lo)[2 * i] = pack2(l0, l1);
    ((uint32_t*)lo)[2 * i + 1] = pack2(l2, l3);
}

__global__ void conv_lc(const float* __restrict__ lck, const float* __restrict__ lcv,
                        float* __restrict__ keyb, float* __restrict__ valb,
                        __nv_bfloat16* __restrict__ khi, __nv_bfloat16* __restrict__ klo,
                        __nv_bfloat16* __restrict__ vhi, __nv_bfloat16* __restrict__ vlo) {
    int i = blockIdx.x * blockDim.x + threadIdx.x;  // 0 .. L*D-1
    int r = i >> 10, c = i & 1023;
    float kv = lck[i], vv = lcv[i];
    size_t o = (size_t)(MR + r) * D + c;
    keyb[o] = kv;
    valb[o] = vv;
    __nv_bfloat16 h, l;
    split2(kv, h, l); khi[o] = h; klo[o] = l;
    split2(vv, h, l); vhi[o] = h; vlo[o] = l;
}

// ---------------- split-bf16 mma.sync GEMM (cp.async, occ 2) -----------------
// Block tile 128x128, 8 warps 4(m)x2(n); K-chunks of 32; row stride 80B.
// Stage = 4 tensors * 128 * 80 = 40KB; 2 stages = 80KB -> 2 CTAs/SM.
#define GRS 80
#define GTEN 10240                // per-tensor bytes per stage
#define GST  40960                // stage size
#define GEMM_SMEM (2 * GST)

__global__ void __launch_bounds__(256, 2) gemm_mma(
    const __nv_bfloat16* __restrict__ Ahi, const __nv_bfloat16* __restrict__ Alo,
    const __nv_bfloat16* __restrict__ Bhi, const __nv_bfloat16* __restrict__ Blo,
    const float* __restrict__ bias, int K, int N, int mode,
    float* __restrict__ f32A, float* __restrict__ f32B,
    __nv_bfloat16* __restrict__ bhA, __nv_bfloat16* __restrict__ blA,
    __nv_bfloat16* __restrict__ bhB, __nv_bfloat16* __restrict__ blB) {
    extern __shared__ char sm[];
    const uint32_t sb = s2u(sm);
    const int tid = threadIdx.x;
    const int lane = tid & 31, wid = tid >> 5;
    const int wm = wid >> 1, wn = wid & 1;
    const int m0 = blockIdx.y * 128, n0 = blockIdx.x * 128;
    const int lrow = lane & 15;
    const int lcolb = (lane >> 4) * 16;

    // cp.async mapping: each 64-thread group owns one tensor; 8 x 16B each
    const int tg = tid >> 6, trem = tid & 63;
    const __nv_bfloat16* gbase =
        (tg == 0) ? Ahi + (size_t)m0 * K :
        (tg == 1) ? Alo + (size_t)m0 * K :
        (tg == 2) ? Bhi + (size_t)n0 * K : Blo + (size_t)n0 * K;

    float acc[2][8][4] = {};

    auto ldchunk = [&](int c, int s) {
        const int k0 = c << 5;
        const uint32_t st = sb + s * GST + tg * GTEN;
#pragma unroll
        for (int i = 0; i < 8; i++) {
            const int rem = trem * 8 + i;
            const int row = rem >> 2, seg = rem & 3;
            cpa16(st + row * GRS + seg * 16, gbase + (size_t)row * K + k0 + seg * 8);
        }
    };

    const int nch = K >> 5;
    ldchunk(0, 0);
    CP_COMMIT();

    for (int c = 0; c < nch; c++) {
        if (c + 1 < nch) {
            ldchunk(c + 1, (c + 1) & 1);
            CP_COMMIT();
            CP_WAIT1();
        } else {
            CP_WAIT0();
        }
        __syncthreads();
        const uint32_t st = sb + (c & 1) * GST;
#pragma unroll
        for (int kt = 0; kt < 2; kt++) {
            uint32_t aH[2][4], aL[2][4];
#pragma unroll
            for (int mf = 0; mf < 2; mf++) {
                const uint32_t ar = (wm * 32 + mf * 16 + lrow) * GRS + kt * 32 + lcolb;
                ldmx4(aH[mf], st + 0 * GTEN + ar);
                ldmx4(aL[mf], st + 1 * GTEN + ar);
            }
#pragma unroll
            for (int nfp = 0; nfp < 4; nfp++) {
                uint32_t r[4], s[4];
                const uint32_t br = (wn * 64 + nfp * 16 + lrow) * GRS + kt * 32 + lcolb;
                ldmx4(r, st + 2 * GTEN + br);
                ldmx4(s, st + 3 * GTEN + br);
#pragma unroll
                for (int mf = 0; mf < 2; mf++) {
                    mma_bf16(acc[mf][2 * nfp], aH[mf], r[0], r[2]);
                    mma_bf16(acc[mf][2 * nfp + 1], aH[mf], r[1], r[3]);
                    mma_bf16(acc[mf][2 * nfp], aH[mf], s[0], s[2]);
                    mma_bf16(acc[mf][2 * nfp + 1], aH[mf], s[1], s[3]);
                    mma_bf16(acc[mf][2 * nfp], aL[mf], r[0], r[2]);
                    mma_bf16(acc[mf][2 * nfp + 1], aL[mf], r[1], r[3]);
                }
            }
        }
        __syncthreads();
    }

    // epilogue
    const int g = lane >> 2, tq = lane & 3;
#pragma unroll
    for (int mf = 0; mf < 2; mf++) {
        const int r0 = m0 + wm * 32 + mf * 16 + g;
        const int r1 = r0 + 8;
#pragma unroll
        for (int nf = 0; nf < 8; nf++) {
            const int col = n0 + wn * 64 + nf * 8 + 2 * tq;
            const float b0 = bias[col], b1 = bias[col + 1];
            float v0 = acc[mf][nf][0] + b0, v1 = acc[mf][nf][1] + b1;
            float v2 = acc[mf][nf][2] + b0, v3 = acc[mf][nf][3] + b1;
            if (mode == 0) {
                *(float2*)(f32A + (size_t)r0 * N + col) = {v0, v1};
                *(float2*)(f32A + (size_t)r1 * N + col) = {v2, v3};
            } else if (mode == 1) {
                __nv_bfloat16 h0, l0, h1, l1;
                split2(v0 * SCALE_LOG2E, h0, l0); split2(v1 * SCALE_LOG2E, h1, l1);
                *(uint32_t*)(bhA + (size_t)r0 * N + col) = pack2(h0, h1);
                *(uint32_t*)(blA + (size_t)r0 * N + col) = pack2(l0, l1);
                split2(v2 * SCALE_LOG2E, h0, l0); split2(v3 * SCALE_LOG2E, h1, l1);
                *(uint32_t*)(bhA + (size_t)r1 * N + col) = pack2(h0, h1);
                *(uint32_t*)(blA + (size_t)r1 * N + col) = pack2(l0, l1);
            } else {
                const int d0 = (r0 < MR) ? r0 : r0 + L_LEN;
                const int d1 = (r1 < MR) ? r1 : r1 + L_LEN;
                float* fdst;
                __nv_bfloat16 *hdst, *ldst;
                int cc;
                if (col < D) { fdst = f32A; hdst = bhA; ldst = blA; cc = col; }
                else         { fdst = f32B; hdst = bhB; ldst = blB; cc = col - D; }
                *(float2*)(fdst + (size_t)d0 * D + cc) = {v0, v1};
                *(float2*)(fdst + (size_t)d1 * D + cc) = {v2, v3};
                __nv_bfloat16 h0, l0, h1, l1;
                split2(v0, h0, l0); split2(v1, h1, l1);
                *(uint32_t*)(hdst + (size_t)d0 * D + cc) = pack2(h0, h1);
                *(uint32_t*)(ldst + (size_t)d0 * D + cc) = pack2(l0, l1);
                split2(v2, h0, l0); split2(v3, h1, l1);
                *(uint32_t*)(hdst + (size_t)d1 * D + cc) = pack2(h0, h1);
                *(uint32_t*)(ldst + (size_t)d1 * D + cc) = pack2(l0, l1);
            }
        }
    }
}

// ---------------- mma.sync flash attention (cp.async, occ 2) -----------------
// grid (QLEN/128, NH), 256 threads (8 warps x 16 q-rows). KV chunks of 64.
// Stage = 4 tensors * 64 * 144B = 36KB; 2 stages + Q(36KB) = 110KB -> 2 CTAs/SM.
// Q fragments reloaded from resident smem each chunk (reg budget <=128).
#define ARS 144
#define ATEN 9216                  // per-tensor bytes per stage (64*144)
#define AST  36864                 // stage size
#define A_QH (2 * AST)
#define A_QL (2 * AST + 18432)
#define ATT_SMEM (2 * AST + 36864)

__global__ void __launch_bounds__(256, 2) attn_mma(
    const __nv_bfloat16* __restrict__ qhi, const __nv_bfloat16* __restrict__ qlo,
    const __nv_bfloat16* __restrict__ khi, const __nv_bfloat16* __restrict__ klo,
    const __nv_bfloat16* __restrict__ vhi, const __nv_bfloat16* __restrict__ vlo,
    __nv_bfloat16* __restrict__ ahi, __nv_bfloat16* __restrict__ alo) {
    extern __shared__ char sm[];
    const uint32_t sb = s2u(sm);
    const int tid = threadIdx.x;
    const int lane = tid & 31, wid = tid >> 5;
    const int h = blockIdx.y;
    const int q0 = blockIdx.x * 128;
    const int lrow = lane & 15;
    const int lcolb = (lane >> 4) * 16;

    // Q tile (128 rows x 64, hi+lo): 2 tensors, 128-thread groups, 8 x 16B each
    {
        const int tg = tid >> 7, trem = tid & 127;
        const __nv_bfloat16* gq = (tg == 0) ? qhi : qlo;
        const uint32_t qs = sb + (tg == 0 ? A_QH : A_QL);
#pragma unroll
        for (int i = 0; i < 8; i++) {
            const int rem = trem * 8 + i;
            const int row = rem >> 3, seg = rem & 7;
            cpa16(qs + row * ARS + seg * 16,
                  gq + (size_t)(q0 + row) * D + h * HD + seg * 8);
        }
    }

    // KV chunk loader: 4 tensors, 64-thread groups, 8 x 16B each
    const int tg = tid >> 6, trem = tid & 63;
    const __nv_bfloat16* gkv =
        (tg == 0) ? khi : (tg == 1) ? klo : (tg == 2) ? vhi : vlo;
    auto ldchunk = [&](int kv0, int s) {
        const uint32_t st = sb + s * AST + tg * ATEN;
#pragma unroll
        for (int i = 0; i < 8; i++) {
            const int rem = trem * 8 + i;
            const int row = rem >> 3, seg = rem & 7;
            cpa16(st + row * ARS + seg * 16,
                  gkv + (size_t)(kv0 + row) * D + h * HD + seg * 8);
        }
    };

    ldchunk(0, 0);
    CP_COMMIT();     // group: Q + chunk0

    float oacc[8][4] = {};
    float lsum0 = 0.f, lsum1 = 0.f;

    const int NCH = KVLEN / 64;  // 60
    for (int c = 0; c < NCH; c++) {
        if (c + 1 < NCH) {
            ldchunk((c + 1) * 64, (c + 1) & 1);
            CP_COMMIT();
            CP_WAIT1();
        } else {
            CP_WAIT0();
        }
        __syncthreads();
        const uint32_t st = sb + (c & 1) * AST;

        float sacc[8][4] = {};
        // S = q . k^T (3-term split); Q frags reloaded from resident smem
#pragma unroll
        for (int kt = 0; kt < 4; kt++) {
            uint32_t qH[4], qL[4];
            const uint32_t ar = (wid * 16 + lrow) * ARS + kt * 32 + lcolb;
            ldmx4(qH, sb + A_QH + ar);
            ldmx4(qL, sb + A_QL + ar);
#pragma unroll
            for (int nfp = 0; nfp < 4; nfp++) {
                uint32_t r[4], s[4];
                const uint32_t br = (nfp * 16 + lrow) * ARS + kt * 32 + lcolb;
                ldmx4(r, st + 0 * ATEN + br);
                ldmx4(s, st + 1 * ATEN + br);
                mma_bf16(sacc[2 * nfp], qH, r[0], r[2]);
                mma_bf16(sacc[2 * nfp + 1], qH, r[1], r[3]);
                mma_bf16(sacc[2 * nfp], qH, s[0], s[2]);
                mma_bf16(sacc[2 * nfp + 1], qH, s[1], s[3]);
                mma_bf16(sacc[2 * nfp], qL, r[0], r[2]);
                mma_bf16(sacc[2 * nfp + 1], qL, r[1], r[3]);
            }
        }
        // p = exp2(S') -> P fragments (hi/lo) -> O += P . V
#pragma unroll
        for (int kt2 = 0; kt2 < 4; kt2++) {
            const float* s0 = sacc[2 * kt2];
            const float* s1 = sacc[2 * kt2 + 1];
            float p0 = exp2f(s0[0]), p1 = exp2f(s0[1]);
            float p2 = exp2f(s0[2]), p3 = exp2f(s0[3]);
            float p4 = exp2f(s1[0]), p5 = exp2f(s1[1]);
            float p6 = exp2f(s1[2]), p7 = exp2f(s1[3]);
            lsum0 += p0 + p1 + p4 + p5;
            lsum1 += p2 + p3 + p6 + p7;
            __nv_bfloat16 h0, l0, h1, l1, h2, l2, h3, l3;
            __nv_bfloat16 h4, l4, h5, l5, h6, l6, h7, l7;
            split2(p0, h0, l0); split2(p1, h1, l1);
            split2(p2, h2, l2); split2(p3, h3, l3);
            split2(p4, h4, l4); split2(p5, h5, l5);
            split2(p6, h6, l6); split2(p7, h7, l7);
            uint32_t aPH[4] = {pack2(h0, h1), pack2(h2, h3), pack2(h4, h5), pack2(h6, h7)};
            uint32_t aPL[4] = {pack2(l0, l1), pack2(l2, l3), pack2(l4, l5), pack2(l6, l7)};
            const int vr0 = kt2 * 16 + ((lane >> 4) << 3) + (lane & 7);
            const uint32_t vcb = ((lane & 8) << 1);
#pragma unroll
            for (int df = 0; df < 4; df++) {
                uint32_t r[4], s[4];
                const uint32_t br = vr0 * ARS + df * 32 + vcb;
                ldmx4t(r, st + 2 * ATEN + br);
                ldmx4t(s, st + 3 * ATEN + br);
                mma_bf16(oacc[2 * df], aPH, r[0], r[2]);
                mma_bf16(oacc[2 * df + 1], aPH, r[1], r[3]);
                mma_bf16(oacc[2 * df], aPH, s[0], s[2]);
                mma_bf16(oacc[2 * df + 1], aPH, s[1], s[3]);
                mma_bf16(oacc[2 * df], aPL, r[0], r[2]);
                mma_bf16(oacc[2 * df + 1], aPL, r[1], r[3]);
            }
        }
        __syncthreads();
    }

    // reduce row sums across the 4 lanes of each quad
#pragma unroll
    for (int off = 1; off <= 2; off <<= 1) {
        lsum0 += __shfl_xor_sync(0xffffffffu, lsum0, off);
        lsum1 += __shfl_xor_sync(0xffffffffu, lsum1, off);
    }
    const float inv0 = 1.0f / lsum0, inv1 = 1.0f / lsum1;

    const int g = lane >> 2, tq = lane & 3;
    const int r0 = q0 + wid * 16 + g, r1 = r0 + 8;
#pragma unroll
    for (int df = 0; df < 8; df++) {
        const int col = df * 8 + 2 * tq;
        __nv_bfloat16 h0, l0, h1, l1;
        split2(oacc[df][0] * inv0, h0, l0); split2(oacc[df][1] * inv0, h1, l1);
        *(uint32_t*)(ahi + (size_t)r0 * D + h * HD + col) = pack2(h0, h1);
        *(uint32_t*)(alo + (size_t)r0 * D + h * HD + col) = pack2(l0, l1);
        split2(oacc[df][2] * inv1, h0, l0); split2(oacc[df][3] * inv1, h1, l1);
        *(uint32_t*)(ahi + (size_t)r1 * D + h * HD + col) = pack2(h0, h1);
        *(uint32_t*)(alo + (size_t)r1 * D + h * HD + col) = pack2(l0, l1);
    }
}

// ---------------------------------------------------------------------------
extern "C" void kernel_launch(void* const* d_in, const int* in_sizes, int n_in,
                              void* d_out, int out_size) {
    const float* ut  = (const float*)d_in[0];
    const float* rc  = (const float*)d_in[1];
    const float* mem = (const float*)d_in[2];
    const float* lck = (const float*)d_in[3];
    const float* lcv = (const float*)d_in[4];
    const float* Wq  = (const float*)d_in[5];
    const float* bq  = (const float*)d_in[6];
    const float* Wkv = (const float*)d_in[7];
    const float* bkv = (const float*)d_in[8];
    const float* Wo  = (const float*)d_in[9];
    const float* bo  = (const float*)d_in[10];

    float* out  = (float*)d_out;
    float* keyb = out + KEY_OFF;
    float* valb = out + VAL_OFF;

    __nv_bfloat16 *qih, *qil, *kvh, *kvl, *wqh, *wql, *wkh, *wkl, *woh, *wol;
    __nv_bfloat16 *qh, *ql, *kh, *kl, *vh, *vl, *ath, *atl;
    cudaGetSymbolAddress((void**)&qih, g_qin_hi);  cudaGetSymbolAddress((void**)&qil, g_qin_lo);
    cudaGetSymbolAddress((void**)&kvh, g_kvin_hi); cudaGetSymbolAddress((void**)&kvl, g_kvin_lo);
    cudaGetSymbolAddress((void**)&wqh, g_wq_hi);   cudaGetSymbolAddress((void**)&wql, g_wq_lo);
    cudaGetSymbolAddress((void**)&wkh, g_wkv_hi);  cudaGetSymbolAddress((void**)&wkl, g_wkv_lo);
    cudaGetSymbolAddress((void**)&woh, g_wo_hi);   cudaGetSymbolAddress((void**)&wol, g_wo_lo);
    cudaGetSymbolAddress((void**)&qh, g_q_hi);     cudaGetSymbolAddress((void**)&ql, g_q_lo);
    cudaGetSymbolAddress((void**)&kh, g_k_hi);     cudaGetSymbolAddress((void**)&kl, g_k_lo);
    cudaGetSymbolAddress((void**)&vh, g_v_hi);     cudaGetSymbolAddress((void**)&vl, g_v_lo);
    cudaGetSymbolAddress((void**)&ath, g_at_hi);   cudaGetSymbolAddress((void**)&atl, g_at_lo);

    cudaFuncSetAttribute(gemm_mma, cudaFuncAttributeMaxDynamicSharedMemorySize, GEMM_SMEM);
    cudaFuncSetAttribute(attn_mma, cudaFuncAttributeMaxDynamicSharedMemorySize, ATT_SMEM);

    auto cs = [](const float* s, __nv_bfloat16* hi, __nv_bfloat16* lo, int n) {
        int n4 = n / 4;
        conv_split<<<(n4 + 255) / 256, 256>>>(s, hi, lo, n4);
    };
    // q_in = [rc ; ut], kv_in = [mem ; rc ; ut]
    cs(rc, qih, qil, R_LEN * D);
    cs(ut, qih + (size_t)R_LEN * D, qil + (size_t)R_LEN * D, U_LEN * D);
    cs(mem, kvh, kvl, M_LEN * D);
    cs(rc, kvh + (size_t)M_LEN * D, kvl + (size_t)M_LEN * D, R_LEN * D);
    cs(ut, kvh + (size_t)MR * D, kvl + (size_t)MR * D, U_LEN * D);
    cs(Wq, wqh, wql, D * D);
    cs(Wkv, wkh, wkl, 2 * D * D);
    cs(Wo, woh, wol, D * D);
    conv_lc<<<(L_LEN * D) / 256, 256>>>(lck, lcv, keyb, valb, kh, kl, vh, vl);

    // q = (q_in @ Wq^T + bq) * 0.125*log2e -> hi/lo
    gemm_mma<<<dim3(D / 128, QLEN / 128), 256, GEMM_SMEM>>>(
        qih, qil, wqh, wql, bq, D, D, 1,
        nullptr, nullptr, qh, ql, nullptr, nullptr);
    // kv = kv_in @ Wkv^T + bkv -> key/value fp32 in d_out (+L-shift) + hi/lo
    gemm_mma<<<dim3(2 * D / 128, KVIN / 128), 256, GEMM_SMEM>>>(
        kvh, kvl, wkh, wkl, bkv, D, 2 * D, 2,
        keyb, valb, kh, kl, vh, vl);
    // attention -> attn hi/lo
    attn_mma<<<dim3(QLEN / 128, NH), 256, ATT_SMEM>>>(
        qh, ql, kh, kl, vh, vl, ath, atl);
    // out = attn @ Wo^T + bo
    gemm_mma<<<dim3(D / 128, QLEN / 128), 256, GEMM_SMEM>>>(
        ath, atl, woh, wol, bo, D, D, 0,
        out, nullptr, nullptr, nullptr, nullptr, nullptr);
}

// round 12
// speedup vs baseline: 1.0697x; 1.0697x over previous
#include <cuda_runtime.h>
#include <cuda_bf16.h>
#include <cstdint>

#define D 1024
#define NH 16
#define HD 64
#define U_LEN 2048
#define R_LEN 256
#define L_LEN 1024
#define M_LEN 512
#define QLEN 2304   // U + R
#define KVLEN 3840  // M + R + L + U
#define KVIN 2816   // M + R + U
#define MR 768      // M + R

#define KEY_OFF (QLEN * D)
#define VAL_OFF (KEY_OFF + KVLEN * D)

#define SCALE_LOG2E 0.1803368801111204f   // 0.125 * log2(e)

// ---------------- scratch (allocation-free rule: __device__ globals) --------
__device__ __nv_bfloat16 g_qin_hi[QLEN * D], g_qin_lo[QLEN * D];
__device__ __nv_bfloat16 g_kvin_hi[KVIN * D], g_kvin_lo[KVIN * D];
__device__ __nv_bfloat16 g_wq_hi[D * D], g_wq_lo[D * D];
__device__ __nv_bfloat16 g_wkv_hi[2 * D * D], g_wkv_lo[2 * D * D];
__device__ __nv_bfloat16 g_wo_hi[D * D], g_wo_lo[D * D];
__device__ __nv_bfloat16 g_q_hi[QLEN * D], g_q_lo[QLEN * D];   // q * 0.125*log2e
__device__ __nv_bfloat16 g_k_hi[KVLEN * D], g_k_lo[KVLEN * D];
__device__ __nv_bfloat16 g_v_hi[KVLEN * D], g_v_lo[KVLEN * D];
__device__ __nv_bfloat16 g_at_hi[QLEN * D], g_at_lo[QLEN * D];

// ---------------- helpers ---------------------------------------------------
static __device__ __forceinline__ uint32_t s2u(const void* p) {
    uint32_t a;
    asm("{ .reg .u64 t; cvta.to.shared.u64 t, %1; cvt.u32.u64 %0, t; }"
        : "=r"(a) : "l"(p));
    return a;
}

static __device__ __forceinline__ void ldmx4(uint32_t* r, uint32_t addr) {
    asm volatile("ldmatrix.sync.aligned.m8n8.x4.shared.b16 {%0,%1,%2,%3}, [%4];"
                 : "=r"(r[0]), "=r"(r[1]), "=r"(r[2]), "=r"(r[3]) : "r"(addr));
}
static __device__ __forceinline__ void ldmx4t(uint32_t* r, uint32_t addr) {
    asm volatile("ldmatrix.sync.aligned.m8n8.x4.trans.shared.b16 {%0,%1,%2,%3}, [%4];"
                 : "=r"(r[0]), "=r"(r[1]), "=r"(r[2]), "=r"(r[3]) : "r"(addr));
}

static __device__ __forceinline__ void mma_bf16(float* c, const uint32_t* a,
                                                uint32_t b0, uint32_t b1) {
    asm volatile("mma.sync.aligned.m16n8k16.row.col.f32.bf16.bf16.f32 "
                 "{%0,%1,%2,%3}, {%4,%5,%6,%7}, {%8,%9}, {%0,%1,%2,%3};"
                 : "+f"(c[0]), "+f"(c[1]), "+f"(c[2]), "+f"(c[3])
                 : "r"(a[0]), "r"(a[1]), "r"(a[2]), "r"(a[3]), "r"(b0), "r"(b1));
}

static __device__ __forceinline__ void cpa16(uint32_t s, const void* g) {
    asm volatile("cp.async.cg.shared.global [%0], [%1], 16;" :: "r"(s), "l"(g));
}
#define CP_COMMIT() asm volatile("cp.async.commit_group;" ::: "memory")
#define CP_WAIT1() asm volatile("cp.async.wait_group 1;" ::: "memory")
#define CP_WAIT0() asm volatile("cp.async.wait_group 0;" ::: "memory")

static __device__ __forceinline__ uint32_t pack2(__nv_bfloat16 a, __nv_bfloat16 b) {
    uint16_t ua = *(uint16_t*)&a, ub = *(uint16_t*)&b;
    return (uint32_t)ua | ((uint32_t)ub << 16);
}
static __device__ __forceinline__ void split2(float x, __nv_bfloat16& h, __nv_bfloat16& l) {
    h = __float2bfloat16(x);
    l = __float2bfloat16(x - __bfloat162float(h));
}

// ---------------- batched conversion kernels ---------------------------------
static __device__ __forceinline__ void conv_seg(const float* __restrict__ s,
                                                __nv_bfloat16* __restrict__ hi,
                                                __nv_bfloat16* __restrict__ lo,
                                                int n4, int i) {
    if (i >= n4) return;
    float4 v = ((const float4*)s)[i];
    __nv_bfloat16 h0, l0, h1, l1, h2, l2, h3, l3;
    split2(v.x, h0, l0); split2(v.y, h1, l1);
    split2(v.z, h2, l2); split2(v.w, h3, l3);
    ((uint32_t*)hi)[2 * i] = pack2(h0, h1);
    ((uint32_t*)hi)[2 * i + 1] = pack2(h2, h3);
    ((uint32_t*)lo)[2 * i] = pack2(l0, l1);
    ((uint32_t*)lo)[2 * i + 1] = pack2(l2, l3);
}

// weights: seg 0 = Wq (1M), 1 = Wkv (2M), 2 = Wo (1M)
__global__ void conv_w(const float* __restrict__ Wq, const float* __restrict__ Wkv,
                       const float* __restrict__ Wo,
                       __nv_bfloat16* wqh, __nv_bfloat16* wql,
                       __nv_bfloat16* wkh, __nv_bfloat16* wkl,
                       __nv_bfloat16* woh, __nv_bfloat16* wol) {
    const int i = blockIdx.x * blockDim.x + threadIdx.x;
    switch (blockIdx.y) {
        case 0: conv_seg(Wq, wqh, wql, D * D / 4, i); break;
        case 1: conv_seg(Wkv, wkh, wkl, 2 * D * D / 4, i); break;
        default: conv_seg(Wo, woh, wol, D * D / 4, i); break;
    }
}

// activations: 0 rc->qin, 1 ut->qin@R, 2 mem->kvin, 3 rc->kvin@M, 4 ut->kvin@MR
__global__ void conv_act(const float* __restrict__ rc, const float* __restrict__ ut,
                         const float* __restrict__ mem,
                         __nv_bfloat16* qih, __nv_bfloat16* qil,
                         __nv_bfloat16* kvh, __nv_bfloat16* kvl) {
    const int i = blockIdx.x * blockDim.x + threadIdx.x;
    switch (blockIdx.y) {
        case 0: conv_seg(rc, qih, qil, R_LEN * D / 4, i); break;
        case 1: conv_seg(ut, qih + (size_t)R_LEN * D, qil + (size_t)R_LEN * D,
                         U_LEN * D / 4, i); break;
        case 2: conv_seg(mem, kvh, kvl, M_LEN * D / 4, i); break;
        case 3: conv_seg(rc, kvh + (size_t)M_LEN * D, kvl + (size_t)M_LEN * D,
                         R_LEN * D / 4, i); break;
        default: conv_seg(ut, kvh + (size_t)MR * D, kvl + (size_t)MR * D,
                          U_LEN * D / 4, i); break;
    }
}

__global__ void conv_lc(const float* __restrict__ lck, const float* __restrict__ lcv,
                        float* __restrict__ keyb, float* __restrict__ valb,
                        __nv_bfloat16* __restrict__ khi, __nv_bfloat16* __restrict__ klo,
                        __nv_bfloat16* __restrict__ vhi, __nv_bfloat16* __restrict__ vlo) {
    int i = blockIdx.x * blockDim.x + threadIdx.x;  // 0 .. L*D-1
    int r = i >> 10, c = i & 1023;
    float kv = lck[i], vv = lcv[i];
    size_t o = (size_t)(MR + r) * D + c;
    keyb[o] = kv;
    valb[o] = vv;
    __nv_bfloat16 h, l;
    split2(kv, h, l); khi[o] = h; klo[o] = l;
    split2(vv, h, l); vhi[o] = h; vlo[o] = l;
}

// ---------------- split-bf16 mma.sync GEMM (cp.async 2-stage) ----------------
// C[M,N] = (Ahi+Alo)[M,K] @ (Bhi+Blo)[N,K]^T + bias (3-term split).
// Block tile 128x128, 8 warps 4(m)x2(n); K-chunks of 64; smem rows 144B.
#define GRS 144
#define GST 73728                 // stage size: 4 tensors * 128 * 144
#define G_AH 0
#define G_AL 18432
#define G_BH 36864
#define G_BL 55296
#define GEMM_SMEM (2 * GST)

__global__ void __launch_bounds__(256, 1) gemm_mma(
    const __nv_bfloat16* __restrict__ Ahi, const __nv_bfloat16* __restrict__ Alo,
    const __nv_bfloat16* __restrict__ Bhi, const __nv_bfloat16* __restrict__ Blo,
    const float* __restrict__ bias, int K, int N, int mode,
    float* __restrict__ f32A, float* __restrict__ f32B,
    __nv_bfloat16* __restrict__ bhA, __nv_bfloat16* __restrict__ blA,
    __nv_bfloat16* __restrict__ bhB, __nv_bfloat16* __restrict__ blB) {
    extern __shared__ char sm[];
    const uint32_t sb = s2u(sm);
    const int tid = threadIdx.x;
    const int lane = tid & 31, wid = tid >> 5;
    const int wm = wid >> 1, wn = wid & 1;
    const int m0 = blockIdx.y * 128, n0 = blockIdx.x * 128;
    const int lrow = lane & 15;
    const int lcolb = (lane >> 4) * 16;
    const int row = tid >> 1, seg = tid & 1;

    float acc[2][8][4] = {};

    auto ldchunk = [&](int c, int s) {
        const int k0 = c << 6;
        const uint32_t st = sb + s * GST;
        const uint32_t so = row * GRS + seg * 64;
        const __nv_bfloat16* ga = Ahi + (size_t)(m0 + row) * K + k0 + seg * 32;
        const __nv_bfloat16* gb = Alo + (size_t)(m0 + row) * K + k0 + seg * 32;
        const __nv_bfloat16* gc = Bhi + (size_t)(n0 + row) * K + k0 + seg * 32;
        const __nv_bfloat16* gd = Blo + (size_t)(n0 + row) * K + k0 + seg * 32;
#pragma unroll
        for (int i = 0; i < 4; i++) {
            cpa16(st + G_AH + so + i * 16, ga + i * 8);
            cpa16(st + G_AL + so + i * 16, gb + i * 8);
            cpa16(st + G_BH + so + i * 16, gc + i * 8);
            cpa16(st + G_BL + so + i * 16, gd + i * 8);
        }
    };

    const int nch = K >> 6;
    ldchunk(0, 0);
    CP_COMMIT();

    for (int c = 0; c < nch; c++) {
        if (c + 1 < nch) {
            ldchunk(c + 1, (c + 1) & 1);
            CP_COMMIT();
            CP_WAIT1();
        } else {
            CP_WAIT0();
        }
        __syncthreads();
        const uint32_t st = sb + (c & 1) * GST;
#pragma unroll
        for (int kt = 0; kt < 4; kt++) {
            uint32_t aH[2][4], aL[2][4];
#pragma unroll
            for (int mf = 0; mf < 2; mf++) {
                const uint32_t ar = (wm * 32 + mf * 16 + lrow) * GRS + kt * 32 + lcolb;
                ldmx4(aH[mf], st + G_AH + ar);
                ldmx4(aL[mf], st + G_AL + ar);
            }
#pragma unroll
            for (int nfp = 0; nfp < 4; nfp++) {
                uint32_t r[4], s[4];
                const uint32_t br = (wn * 64 + nfp * 16 + lrow) * GRS + kt * 32 + lcolb;
                ldmx4(r, st + G_BH + br);
                ldmx4(s, st + G_BL + br);
#pragma unroll
                for (int mf = 0; mf < 2; mf++) {
                    mma_bf16(acc[mf][2 * nfp], aH[mf], r[0], r[2]);
                    mma_bf16(acc[mf][2 * nfp + 1], aH[mf], r[1], r[3]);
                    mma_bf16(acc[mf][2 * nfp], aH[mf], s[0], s[2]);
                    mma_bf16(acc[mf][2 * nfp + 1], aH[mf], s[1], s[3]);
                    mma_bf16(acc[mf][2 * nfp], aL[mf], r[0], r[2]);
                    mma_bf16(acc[mf][2 * nfp + 1], aL[mf], r[1], r[3]);
                }
            }
        }
        __syncthreads();
    }

    // epilogue
    const int g = lane >> 2, tq = lane & 3;
#pragma unroll
    for (int mf = 0; mf < 2; mf++) {
        const int r0 = m0 + wm * 32 + mf * 16 + g;
        const int r1 = r0 + 8;
#pragma unroll
        for (int nf = 0; nf < 8; nf++) {
            const int col = n0 + wn * 64 + nf * 8 + 2 * tq;
            const float b0 = bias[col], b1 = bias[col + 1];
            float v0 = acc[mf][nf][0] + b0, v1 = acc[mf][nf][1] + b1;
            float v2 = acc[mf][nf][2] + b0, v3 = acc[mf][nf][3] + b1;
            if (mode == 0) {
                *(float2*)(f32A + (size_t)r0 * N + col) = {v0, v1};
                *(float2*)(f32A + (size_t)r1 * N + col) = {v2, v3};
            } else if (mode == 1) {
                __nv_bfloat16 h0, l0, h1, l1;
                split2(v0 * SCALE_LOG2E, h0, l0); split2(v1 * SCALE_LOG2E, h1, l1);
                *(uint32_t*)(bhA + (size_t)r0 * N + col) = pack2(h0, h1);
                *(uint32_t*)(blA + (size_t)r0 * N + col) = pack2(l0, l1);
                split2(v2 * SCALE_LOG2E, h0, l0); split2(v3 * SCALE_LOG2E, h1, l1);
                *(uint32_t*)(bhA + (size_t)r1 * N + col) = pack2(h0, h1);
                *(uint32_t*)(blA + (size_t)r1 * N + col) = pack2(l0, l1);
            } else {
                const int d0 = (r0 < MR) ? r0 : r0 + L_LEN;
                const int d1 = (r1 < MR) ? r1 : r1 + L_LEN;
                float* fdst;
                __nv_bfloat16 *hdst, *ldst;
                int cc;
                if (col < D) { fdst = f32A; hdst = bhA; ldst = blA; cc = col; }
                else         { fdst = f32B; hdst = bhB; ldst = blB; cc = col - D; }
                *(float2*)(fdst + (size_t)d0 * D + cc) = {v0, v1};
                *(float2*)(fdst + (size_t)d1 * D + cc) = {v2, v3};
                __nv_bfloat16 h0, l0, h1, l1;
                split2(v0, h0, l0); split2(v1, h1, l1);
                *(uint32_t*)(hdst + (size_t)d0 * D + cc) = pack2(h0, h1);
                *(uint32_t*)(ldst + (size_t)d0 * D + cc) = pack2(l0, l1);
                split2(v2, h0, l0); split2(v3, h1, l1);
                *(uint32_t*)(hdst + (size_t)d1 * D + cc) = pack2(h0, h1);
                *(uint32_t*)(ldst + (size_t)d1 * D + cc) = pack2(l0, l1);
            }
        }
    }
}

// ---------------- mma.sync flash attention (cp.async 2-stage) ----------------
// grid (QLEN/128, NH), 256 threads (8 warps x 16 q-rows). KV chunks of 128.
// V row-major [kv][d]; PV B-fragments via ldmatrix.trans.
// No-max softmax (logits bounded): p = exp2(S'), O accumulates in regs.
#define A_KH 0
#define A_KL 18432
#define A_VH 36864
#define A_VL 55296
#define AST 73728                  // stage size
#define A_QH (2 * AST)
#define A_QL (2 * AST + 18432)
#define ATT_SMEM (2 * AST + 36864)

__global__ void __launch_bounds__(256, 1) attn_mma(
    const __nv_bfloat16* __restrict__ qhi, const __nv_bfloat16* __restrict__ qlo,
    const __nv_bfloat16* __restrict__ khi, const __nv_bfloat16* __restrict__ klo,
    const __nv_bfloat16* __restrict__ vhi, const __nv_bfloat16* __restrict__ vlo,
    __nv_bfloat16* __restrict__ ahi, __nv_bfloat16* __restrict__ alo) {
    extern __shared__ char sm[];
    const uint32_t sb = s2u(sm);
    const int tid = threadIdx.x;
    const int lane = tid & 31, wid = tid >> 5;
    const int h = blockIdx.y;
    const int q0 = blockIdx.x * 128;
    const int lrow = lane & 15;
    const int lcolb = (lane >> 4) * 16;
    const int row = tid >> 1, seg = tid & 1;

    // Q tile via cp.async (group 0)
    {
        const uint32_t so = row * GRS + seg * 64;
        const __nv_bfloat16* ph = qhi + (size_t)(q0 + row) * D + h * HD + seg * 32;
        const __nv_bfloat16* pl = qlo + (size_t)(q0 + row) * D + h * HD + seg * 32;
#pragma unroll
        for (int i = 0; i < 4; i++) {
            cpa16(sb + A_QH + so + i * 16, ph + i * 8);
            cpa16(sb + A_QL + so + i * 16, pl + i * 8);
        }
    }
    CP_COMMIT();

    auto ldchunk = [&](int kv0, int s) {
        const uint32_t st = sb + s * AST;
        const uint32_t so = row * GRS + seg * 64;
        const __nv_bfloat16* pkh = khi + (size_t)(kv0 + row) * D + h * HD + seg * 32;
        const __nv_bfloat16* pkl = klo + (size_t)(kv0 + row) * D + h * HD + seg * 32;
        const __nv_bfloat16* pvh = vhi + (size_t)(kv0 + row) * D + h * HD + seg * 32;
        const __nv_bfloat16* pvl = vlo + (size_t)(kv0 + row) * D + h * HD + seg * 32;
#pragma unroll
        for (int i = 0; i < 4; i++) {
            cpa16(st + A_KH + so + i * 16, pkh + i * 8);
            cpa16(st + A_KL + so + i * 16, pkl + i * 8);
            cpa16(st + A_VH + so + i * 16, pvh + i * 8);
            cpa16(st + A_VL + so + i * 16, pvl + i * 8);
        }
    };

    ldchunk(0, 0);
    CP_COMMIT();

    // wait for Q (leave KV chunk 0 pending), load Q fragments
    CP_WAIT1();
    __syncthreads();
    uint32_t qH[4][4], qL[4][4];
#pragma unroll
    for (int kt = 0; kt < 4; kt++) {
        const uint32_t ar = (wid * 16 + lrow) * GRS + kt * 32 + lcolb;
        ldmx4(qH[kt], sb + A_QH + ar);
        ldmx4(qL[kt], sb + A_QL + ar);
    }

    float oacc[8][4] = {};
    float lsum0 = 0.f, lsum1 = 0.f;

    const int NCH = KVLEN / 128;  // 30
    for (int c = 0; c < NCH; c++) {
        if (c + 1 < NCH) {
            ldchunk((c + 1) * 128, (c + 1) & 1);
            CP_COMMIT();
            CP_WAIT1();
        } else {
            CP_WAIT0();
        }
        __syncthreads();
        const uint32_t st = sb + (c & 1) * AST;

#pragma unroll
        for (int half = 0; half < 2; half++) {
            float sacc[8][4] = {};
            // S = q . k^T  (3-term split)
#pragma unroll
            for (int kt = 0; kt < 4; kt++) {
#pragma unroll
                for (int nfp = 0; nfp < 4; nfp++) {
                    uint32_t r[4], s[4];
                    const uint32_t br =
                        (half * 64 + nfp * 16 + lrow) * GRS + kt * 32 + lcolb;
                    ldmx4(r, st + A_KH + br);
                    ldmx4(s, st + A_KL + br);
                    mma_bf16(sacc[2 * nfp], qH[kt], r[0], r[2]);
                    mma_bf16(sacc[2 * nfp + 1], qH[kt], r[1], r[3]);
                    mma_bf16(sacc[2 * nfp], qH[kt], s[0], s[2]);
                    mma_bf16(sacc[2 * nfp + 1], qH[kt], s[1], s[3]);
                    mma_bf16(sacc[2 * nfp], qL[kt], r[0], r[2]);
                    mma_bf16(sacc[2 * nfp + 1], qL[kt], r[1], r[3]);
                }
            }
            // p = exp2(S') -> P fragments (hi/lo) -> O += P . V
#pragma unroll
            for (int kt2 = 0; kt2 < 4; kt2++) {
                const float* s0 = sacc[2 * kt2];
                const float* s1 = sacc[2 * kt2 + 1];
                float p0 = exp2f(s0[0]), p1 = exp2f(s0[1]);
                float p2 = exp2f(s0[2]), p3 = exp2f(s0[3]);
                float p4 = exp2f(s1[0]), p5 = exp2f(s1[1]);
                float p6 = exp2f(s1[2]), p7 = exp2f(s1[3]);
                lsum0 += p0 + p1 + p4 + p5;
                lsum1 += p2 + p3 + p6 + p7;
                __nv_bfloat16 h0, l0, h1, l1, h2, l2, h3, l3;
                __nv_bfloat16 h4, l4, h5, l5, h6, l6, h7, l7;
                split2(p0, h0, l0); split2(p1, h1, l1);
                split2(p2, h2, l2); split2(p3, h3, l3);
                split2(p4, h4, l4); split2(p5, h5, l5);
                split2(p6, h6, l6); split2(p7, h7, l7);
                uint32_t aPH[4] = {pack2(h0, h1), pack2(h2, h3), pack2(h4, h5), pack2(h6, h7)};
                uint32_t aPL[4] = {pack2(l0, l1), pack2(l2, l3), pack2(l4, l5), pack2(l6, l7)};
                // V fragments via ldmatrix.trans on row-major V
                const int vr0 = (half * 4 + kt2) * 16 + ((lane >> 4) << 3) + (lane & 7);
                const uint32_t vcb = ((lane & 8) << 1);
#pragma unroll
                for (int df = 0; df < 4; df++) {
                    uint32_t r[4], s[4];
                    const uint32_t br = vr0 * GRS + df * 32 + vcb;
                    ldmx4t(r, st + A_VH + br);
                    ldmx4t(s, st + A_VL + br);
                    mma_bf16(oacc[2 * df], aPH, r[0], r[2]);
                    mma_bf16(oacc[2 * df + 1], aPH, r[1], r[3]);
                    mma_bf16(oacc[2 * df], aPH, s[0], s[2]);
                    mma_bf16(oacc[2 * df + 1], aPH, s[1], s[3]);
                    mma_bf16(oacc[2 * df], aPL, r[0], r[2]);
                    mma_bf16(oacc[2 * df + 1], aPL, r[1], r[3]);
                }
            }
        }
        __syncthreads();
    }

    // reduce row sums across the 4 lanes of each quad
#pragma unroll
    for (int off = 1; off <= 2; off <<= 1) {
        lsum0 += __shfl_xor_sync(0xffffffffu, lsum0, off);
        lsum1 += __shfl_xor_sync(0xffffffffu, lsum1, off);
    }
    const float inv0 = 1.0f / lsum0, inv1 = 1.0f / lsum1;

    const int g = lane >> 2, tq = lane & 3;
    const int r0 = q0 + wid * 16 + g, r1 = r0 + 8;
#pragma unroll
    for (int df = 0; df < 8; df++) {
        const int col = df * 8 + 2 * tq;
        __nv_bfloat16 h0, l0, h1, l1;
        split2(oacc[df][0] * inv0, h0, l0); split2(oacc[df][1] * inv0, h1, l1);
        *(uint32_t*)(ahi + (size_t)r0 * D + h * HD + col) = pack2(h0, h1);
        *(uint32_t*)(alo + (size_t)r0 * D + h * HD + col) = pack2(l0, l1);
        split2(oacc[df][2] * inv1, h0, l0); split2(oacc[df][3] * inv1, h1, l1);
        *(uint32_t*)(ahi + (size_t)r1 * D + h * HD + col) = pack2(h0, h1);
        *(uint32_t*)(alo + (size_t)r1 * D + h * HD + col) = pack2(l0, l1);
    }
}

// ---------------------------------------------------------------------------
extern "C" void kernel_launch(void* const* d_in, const int* in_sizes, int n_in,
                              void* d_out, int out_size) {
    const float* ut  = (const float*)d_in[0];
    const float* rc  = (const float*)d_in[1];
    const float* mem = (const float*)d_in[2];
    const float* lck = (const float*)d_in[3];
    const float* lcv = (const float*)d_in[4];
    const float* Wq  = (const float*)d_in[5];
    const float* bq  = (const float*)d_in[6];
    const float* Wkv = (const float*)d_in[7];
    const float* bkv = (const float*)d_in[8];
    const float* Wo  = (const float*)d_in[9];
    const float* bo  = (const float*)d_in[10];

    float* out  = (float*)d_out;
    float* keyb = out + KEY_OFF;
    float* valb = out + VAL_OFF;

    __nv_bfloat16 *qih, *qil, *kvh, *kvl, *wqh, *wql, *wkh, *wkl, *woh, *wol;
    __nv_bfloat16 *qh, *ql, *kh, *kl, *vh, *vl, *ath, *atl;
    cudaGetSymbolAddress((void**)&qih, g_qin_hi);  cudaGetSymbolAddress((void**)&qil, g_qin_lo);
    cudaGetSymbolAddress((void**)&kvh, g_kvin_hi); cudaGetSymbolAddress((void**)&kvl, g_kvin_lo);
    cudaGetSymbolAddress((void**)&wqh, g_wq_hi);   cudaGetSymbolAddress((void**)&wql, g_wq_lo);
    cudaGetSymbolAddress((void**)&wkh, g_wkv_hi);  cudaGetSymbolAddress((void**)&wkl, g_wkv_lo);
    cudaGetSymbolAddress((void**)&woh, g_wo_hi);   cudaGetSymbolAddress((void**)&wol, g_wo_lo);
    cudaGetSymbolAddress((void**)&qh, g_q_hi);     cudaGetSymbolAddress((void**)&ql, g_q_lo);
    cudaGetSymbolAddress((void**)&kh, g_k_hi);     cudaGetSymbolAddress((void**)&kl, g_k_lo);
    cudaGetSymbolAddress((void**)&vh, g_v_hi);     cudaGetSymbolAddress((void**)&vl, g_v_lo);
    cudaGetSymbolAddress((void**)&ath, g_at_hi);   cudaGetSymbolAddress((void**)&atl, g_at_lo);

    cudaFuncSetAttribute(gemm_mma, cudaFuncAttributeMaxDynamicSharedMemorySize, GEMM_SMEM);
    cudaFuncSetAttribute(attn_mma, cudaFuncAttributeMaxDynamicSharedMemorySize, ATT_SMEM);

    // launch 0: weights (max seg n4 = 524288 -> 2048 blocks)
    conv_w<<<dim3(2048, 3), 256>>>(Wq, Wkv, Wo, wqh, wql, wkh, wkl, woh, wol);
    // launch 1: activations (max seg n4 = 524288)
    conv_act<<<dim3(2048, 5), 256>>>(rc, ut, mem, qih, qil, kvh, kvl);
    // launch 2: left-context
    conv_lc<<<(L_LEN * D) / 256, 256>>>(lck, lcv, keyb, valb, kh, kl, vh, vl);

    // launch 3: q = (q_in @ Wq^T + bq) * 0.125*log2e -> hi/lo
    gemm_mma<<<dim3(D / 128, QLEN / 128), 256, GEMM_SMEM>>>(
        qih, qil, wqh, wql, bq, D, D, 1,
        nullptr, nullptr, qh, ql, nullptr, nullptr);
    // launch 4: kv = kv_in @ Wkv^T + bkv -> key/value fp32 in d_out (+L-shift) + hi/lo
    gemm_mma<<<dim3(2 * D / 128, KVIN / 128), 256, GEMM_SMEM>>>(
        kvh, kvl, wkh, wkl, bkv, D, 2 * D, 2,
        keyb, valb, kh, kl, vh, vl);
    // launch 5 (ncu -s 5 target): attention -> attn hi/lo
    attn_mma<<<dim3(QLEN / 128, NH), 256, ATT_SMEM>>>(
        qh, ql, kh, kl, vh, vl, ath, atl);
    // launch 6: out = attn @ Wo^T + bo
    gemm_mma<<<dim3(D / 128, QLEN / 128), 256, GEMM_SMEM>>>(
        ath, atl, woh, wol, bo, D, D, 0,
        out, nullptr, nullptr, nullptr, nullptr, nullptr);
}

// round 13
// speedup vs baseline: 1.2365x; 1.1559x over previous
#include <cuda_runtime.h>
#include <cuda_bf16.h>
#include <cstdint>

#define D 1024
#define NH 16
#define HD 64
#define U_LEN 2048
#define R_LEN 256
#define L_LEN 1024
#define M_LEN 512
#define QLEN 2304   // U + R
#define KVLEN 3840  // M + R + L + U
#define KVIN 2816   // M + R + U
#define MR 768      // M + R

#define KEY_OFF (QLEN * D)
#define VAL_OFF (KEY_OFF + KVLEN * D)

#define SCALE_LOG2E 0.1803368801111204f   // 0.125 * log2(e)

// ---------------- scratch (allocation-free rule: __device__ globals) --------
__device__ __nv_bfloat16 g_qin_hi[QLEN * D], g_qin_lo[QLEN * D];
__device__ __nv_bfloat16 g_kvin_hi[KVIN * D], g_kvin_lo[KVIN * D];
__device__ __nv_bfloat16 g_wq_hi[D * D], g_wq_lo[D * D];
__device__ __nv_bfloat16 g_wkv_hi[2 * D * D], g_wkv_lo[2 * D * D];
__device__ __nv_bfloat16 g_wo_hi[D * D], g_wo_lo[D * D];
__device__ __nv_bfloat16 g_q_hi[QLEN * D], g_q_lo[QLEN * D];   // q * 0.125*log2e
__device__ __nv_bfloat16 g_k_hi[KVLEN * D], g_k_lo[KVLEN * D];
__device__ __nv_bfloat16 g_v_hi[KVLEN * D], g_v_lo[KVLEN * D];
__device__ __nv_bfloat16 g_at_hi[QLEN * D], g_at_lo[QLEN * D];

// ---------------- helpers ---------------------------------------------------
static __device__ __forceinline__ uint32_t s2u(const void* p) {
    uint32_t a;
    asm("{ .reg .u64 t; cvta.to.shared.u64 t, %1; cvt.u32.u64 %0, t; }"
        : "=r"(a) : "l"(p));
    return a;
}

static __device__ __forceinline__ void ldmx4(uint32_t* r, uint32_t addr) {
    asm volatile("ldmatrix.sync.aligned.m8n8.x4.shared.b16 {%0,%1,%2,%3}, [%4];"
                 : "=r"(r[0]), "=r"(r[1]), "=r"(r[2]), "=r"(r[3]) : "r"(addr));
}
static __device__ __forceinline__ void ldmx4t(uint32_t* r, uint32_t addr) {
    asm volatile("ldmatrix.sync.aligned.m8n8.x4.trans.shared.b16 {%0,%1,%2,%3}, [%4];"
                 : "=r"(r[0]), "=r"(r[1]), "=r"(r[2]), "=r"(r[3]) : "r"(addr));
}

static __device__ __forceinline__ void mma_bf16(float* c, const uint32_t* a,
                                                uint32_t b0, uint32_t b1) {
    asm volatile("mma.sync.aligned.m16n8k16.row.col.f32.bf16.bf16.f32 "
                 "{%0,%1,%2,%3}, {%4,%5,%6,%7}, {%8,%9}, {%0,%1,%2,%3};"
                 : "+f"(c[0]), "+f"(c[1]), "+f"(c[2]), "+f"(c[3])
                 : "r"(a[0]), "r"(a[1]), "r"(a[2]), "r"(a[3]), "r"(b0), "r"(b1));
}

static __device__ __forceinline__ void cpa16(uint32_t s, const void* g) {
    asm volatile("cp.async.cg.shared.global [%0], [%1], 16;" :: "r"(s), "l"(g));
}
#define CP_COMMIT() asm volatile("cp.async.commit_group;" ::: "memory")
#define CP_WAIT1() asm volatile("cp.async.wait_group 1;" ::: "memory")
#define CP_WAIT0() asm volatile("cp.async.wait_group 0;" ::: "memory")

static __device__ __forceinline__ uint32_t pack2(__nv_bfloat16 a, __nv_bfloat16 b) {
    uint16_t ua = *(uint16_t*)&a, ub = *(uint16_t*)&b;
    return (uint32_t)ua | ((uint32_t)ub << 16);
}
static __device__ __forceinline__ void split2(float x, __nv_bfloat16& h, __nv_bfloat16& l) {
    h = __float2bfloat16(x);
    l = __float2bfloat16(x - __bfloat162float(h));
}

// ---------------- batched conversion kernels ---------------------------------
static __device__ __forceinline__ void conv_seg(const float* __restrict__ s,
                                                __nv_bfloat16* __restrict__ hi,
                                                __nv_bfloat16* __restrict__ lo,
                                                int n4, int i) {
    if (i >= n4) return;
    float4 v = ((const float4*)s)[i];
    __nv_bfloat16 h0, l0, h1, l1, h2, l2, h3, l3;
    split2(v.x, h0, l0); split2(v.y, h1, l1);
    split2(v.z, h2, l2); split2(v.w, h3, l3);
    ((uint32_t*)hi)[2 * i] = pack2(h0, h1);
    ((uint32_t*)hi)[2 * i + 1] = pack2(h2, h3);
    ((uint32_t*)lo)[2 * i] = pack2(l0, l1);
    ((uint32_t*)lo)[2 * i + 1] = pack2(l2, l3);
}

__global__ void conv_w(const float* __restrict__ Wq, const float* __restrict__ Wkv,
                       const float* __restrict__ Wo,
                       __nv_bfloat16* wqh, __nv_bfloat16* wql,
                       __nv_bfloat16* wkh, __nv_bfloat16* wkl,
                       __nv_bfloat16* woh, __nv_bfloat16* wol) {
    const int i = blockIdx.x * blockDim.x + threadIdx.x;
    switch (blockIdx.y) {
        case 0: conv_seg(Wq, wqh, wql, D * D / 4, i); break;
        case 1: conv_seg(Wkv, wkh, wkl, 2 * D * D / 4, i); break;
        default: conv_seg(Wo, woh, wol, D * D / 4, i); break;
    }
}

__global__ void conv_act(const float* __restrict__ rc, const float* __restrict__ ut,
                         const float* __restrict__ mem,
                         __nv_bfloat16* qih, __nv_bfloat16* qil,
                         __nv_bfloat16* kvh, __nv_bfloat16* kvl) {
    const int i = blockIdx.x * blockDim.x + threadIdx.x;
    switch (blockIdx.y) {
        case 0: conv_seg(rc, qih, qil, R_LEN * D / 4, i); break;
        case 1: conv_seg(ut, qih + (size_t)R_LEN * D, qil + (size_t)R_LEN * D,
                         U_LEN * D / 4, i); break;
        case 2: conv_seg(mem, kvh, kvl, M_LEN * D / 4, i); break;
        case 3: conv_seg(rc, kvh + (size_t)M_LEN * D, kvl + (size_t)M_LEN * D,
                         R_LEN * D / 4, i); break;
        default: conv_seg(ut, kvh + (size_t)MR * D, kvl + (size_t)MR * D,
                          U_LEN * D / 4, i); break;
    }
}

__global__ void conv_lc(const float* __restrict__ lck, const float* __restrict__ lcv,
                        float* __restrict__ keyb, float* __restrict__ valb,
                        __nv_bfloat16* __restrict__ khi, __nv_bfloat16* __restrict__ klo,
                        __nv_bfloat16* __restrict__ vhi, __nv_bfloat16* __restrict__ vlo) {
    int i = blockIdx.x * blockDim.x + threadIdx.x;  // 0 .. L*D-1
    int r = i >> 10, c = i & 1023;
    float kv = lck[i], vv = lcv[i];
    size_t o = (size_t)(MR + r) * D + c;
    keyb[o] = kv;
    valb[o] = vv;
    __nv_bfloat16 h, l;
    split2(kv, h, l); khi[o] = h; klo[o] = l;
    split2(vv, h, l); vhi[o] = h; vlo[o] = l;
}

// ---------------- split-bf16 mma.sync GEMM (512 thr, 16 warps 4x4) -----------
// C[M,N] = (Ahi+Alo)[M,K] @ (Bhi+Blo)[N,K]^T + bias (3-term split).
// Block tile 128x128, warp tile 32x32; K-chunks of 64; smem rows 144B.
#define GRS 144
#define GST 73728                 // stage size: 4 tensors * 128 * 144
#define G_AH 0
#define G_AL 18432
#define G_BH 36864
#define G_BL 55296
#define GEMM_SMEM (2 * GST)

__global__ void __launch_bounds__(512, 1) gemm_mma(
    const __nv_bfloat16* __restrict__ Ahi, const __nv_bfloat16* __restrict__ Alo,
    const __nv_bfloat16* __restrict__ Bhi, const __nv_bfloat16* __restrict__ Blo,
    const float* __restrict__ bias, int K, int N, int mode,
    float* __restrict__ f32A, float* __restrict__ f32B,
    __nv_bfloat16* __restrict__ bhA, __nv_bfloat16* __restrict__ blA,
    __nv_bfloat16* __restrict__ bhB, __nv_bfloat16* __restrict__ blB) {
    extern __shared__ char sm[];
    const uint32_t sb = s2u(sm);
    const int tid = threadIdx.x;
    const int lane = tid & 31, wid = tid >> 5;
    const int wm = wid >> 2, wn = wid & 3;
    const int m0 = blockIdx.y * 128, n0 = blockIdx.x * 128;
    const int lrow = lane & 15;
    const int lcolb = (lane >> 4) * 16;
    const int row = tid >> 2, seg = tid & 3;   // loader: 128 rows x 4 segs of 32B

    float acc[2][4][4] = {};

    auto ldchunk = [&](int c, int s) {
        const int k0 = c << 6;
        const uint32_t st = sb + s * GST;
        const uint32_t so = row * GRS + seg * 32;
        const __nv_bfloat16* ga = Ahi + (size_t)(m0 + row) * K + k0 + seg * 16;
        const __nv_bfloat16* gb = Alo + (size_t)(m0 + row) * K + k0 + seg * 16;
        const __nv_bfloat16* gc = Bhi + (size_t)(n0 + row) * K + k0 + seg * 16;
        const __nv_bfloat16* gd = Blo + (size_t)(n0 + row) * K + k0 + seg * 16;
        cpa16(st + G_AH + so, ga);       cpa16(st + G_AH + so + 16, ga + 8);
        cpa16(st + G_AL + so, gb);       cpa16(st + G_AL + so + 16, gb + 8);
        cpa16(st + G_BH + so, gc);       cpa16(st + G_BH + so + 16, gc + 8);
        cpa16(st + G_BL + so, gd);       cpa16(st + G_BL + so + 16, gd + 8);
    };

    const int nch = K >> 6;
    ldchunk(0, 0);
    CP_COMMIT();

    for (int c = 0; c < nch; c++) {
        if (c + 1 < nch) {
            ldchunk(c + 1, (c + 1) & 1);
            CP_COMMIT();
            CP_WAIT1();
        } else {
            CP_WAIT0();
        }
        __syncthreads();
        const uint32_t st = sb + (c & 1) * GST;
#pragma unroll
        for (int kt = 0; kt < 4; kt++) {
            uint32_t aH[2][4], aL[2][4];
#pragma unroll
            for (int mf = 0; mf < 2; mf++) {
                const uint32_t ar = (wm * 32 + mf * 16 + lrow) * GRS + kt * 32 + lcolb;
                ldmx4(aH[mf], st + G_AH + ar);
                ldmx4(aL[mf], st + G_AL + ar);
            }
#pragma unroll
            for (int nfp = 0; nfp < 2; nfp++) {
                uint32_t r[4], s[4];
                const uint32_t br = (wn * 32 + nfp * 16 + lrow) * GRS + kt * 32 + lcolb;
                ldmx4(r, st + G_BH + br);
                ldmx4(s, st + G_BL + br);
#pragma unroll
                for (int mf = 0; mf < 2; mf++) {
                    mma_bf16(acc[mf][2 * nfp], aH[mf], r[0], r[2]);
                    mma_bf16(acc[mf][2 * nfp + 1], aH[mf], r[1], r[3]);
                    mma_bf16(acc[mf][2 * nfp], aH[mf], s[0], s[2]);
                    mma_bf16(acc[mf][2 * nfp + 1], aH[mf], s[1], s[3]);
                    mma_bf16(acc[mf][2 * nfp], aL[mf], r[0], r[2]);
                    mma_bf16(acc[mf][2 * nfp + 1], aL[mf], r[1], r[3]);
                }
            }
        }
        __syncthreads();
    }

    // epilogue
    const int g = lane >> 2, tq = lane & 3;
#pragma unroll
    for (int mf = 0; mf < 2; mf++) {
        const int r0 = m0 + wm * 32 + mf * 16 + g;
        const int r1 = r0 + 8;
#pragma unroll
        for (int nf = 0; nf < 4; nf++) {
            const int col = n0 + wn * 32 + nf * 8 + 2 * tq;
            const float b0 = bias[col], b1 = bias[col + 1];
            float v0 = acc[mf][nf][0] + b0, v1 = acc[mf][nf][1] + b1;
            float v2 = acc[mf][nf][2] + b0, v3 = acc[mf][nf][3] + b1;
            if (mode == 0) {
                *(float2*)(f32A + (size_t)r0 * N + col) = {v0, v1};
                *(float2*)(f32A + (size_t)r1 * N + col) = {v2, v3};
            } else if (mode == 1) {
                __nv_bfloat16 h0, l0, h1, l1;
                split2(v0 * SCALE_LOG2E, h0, l0); split2(v1 * SCALE_LOG2E, h1, l1);
                *(uint32_t*)(bhA + (size_t)r0 * N + col) = pack2(h0, h1);
                *(uint32_t*)(blA + (size_t)r0 * N + col) = pack2(l0, l1);
                split2(v2 * SCALE_LOG2E, h0, l0); split2(v3 * SCALE_LOG2E, h1, l1);
                *(uint32_t*)(bhA + (size_t)r1 * N + col) = pack2(h0, h1);
                *(uint32_t*)(blA + (size_t)r1 * N + col) = pack2(l0, l1);
            } else {
                const int d0 = (r0 < MR) ? r0 : r0 + L_LEN;
                const int d1 = (r1 < MR) ? r1 : r1 + L_LEN;
                float* fdst;
                __nv_bfloat16 *hdst, *ldst;
                int cc;
                if (col < D) { fdst = f32A; hdst = bhA; ldst = blA; cc = col; }
                else         { fdst = f32B; hdst = bhB; ldst = blB; cc = col - D; }
                *(float2*)(fdst + (size_t)d0 * D + cc) = {v0, v1};
                *(float2*)(fdst + (size_t)d1 * D + cc) = {v2, v3};
                __nv_bfloat16 h0, l0, h1, l1;
                split2(v0, h0, l0); split2(v1, h1, l1);
                *(uint32_t*)(hdst + (size_t)d0 * D + cc) = pack2(h0, h1);
                *(uint32_t*)(ldst + (size_t)d0 * D + cc) = pack2(l0, l1);
                split2(v2, h0, l0); split2(v3, h1, l1);
                *(uint32_t*)(hdst + (size_t)d1 * D + cc) = pack2(h0, h1);
                *(uint32_t*)(ldst + (size_t)d1 * D + cc) = pack2(l0, l1);
            }
        }
    }
}

// ---------------- mma.sync flash attention (512 thr, kv-split warps) ---------
// grid (QLEN/128, NH). 16 warps = 8 q-groups x 2 kv-halves. KV chunks of 128;
// each warp computes S and partial O for its 64-kv half; partials accumulate
// in registers across all chunks; one smem reduction at the end.
#define A_KH 0
#define A_KL 18432
#define A_VH 36864
#define A_VL 55296
#define AST 73728                  // stage size
#define A_QH (2 * AST)
#define A_QL (2 * AST + 18432)
#define ATT_SMEM (2 * AST + 36864)

__global__ void __launch_bounds__(512, 1) attn_mma(
    const __nv_bfloat16* __restrict__ qhi, const __nv_bfloat16* __restrict__ qlo,
    const __nv_bfloat16* __restrict__ khi, const __nv_bfloat16* __restrict__ klo,
    const __nv_bfloat16* __restrict__ vhi, const __nv_bfloat16* __restrict__ vlo,
    __nv_bfloat16* __restrict__ ahi, __nv_bfloat16* __restrict__ alo) {
    extern __shared__ char sm[];
    const uint32_t sb = s2u(sm);
    const int tid = threadIdx.x;
    const int lane = tid & 31, wid = tid >> 5;
    const int qw = wid >> 1, kw = wid & 1;   // q-group 0..7, kv-half 0..1
    const int h = blockIdx.y;
    const int q0 = blockIdx.x * 128;
    const int lrow = lane & 15;
    const int lcolb = (lane >> 4) * 16;
    const int row = tid >> 2, seg = tid & 3;

    // Q tile via cp.async (group 0): 2 tensors, 128 rows x 128B
    {
        const uint32_t so = row * GRS + seg * 32;
        const __nv_bfloat16* ph = qhi + (size_t)(q0 + row) * D + h * HD + seg * 16;
        const __nv_bfloat16* pl = qlo + (size_t)(q0 + row) * D + h * HD + seg * 16;
        cpa16(sb + A_QH + so, ph);      cpa16(sb + A_QH + so + 16, ph + 8);
        cpa16(sb + A_QL + so, pl);      cpa16(sb + A_QL + so + 16, pl + 8);
    }
    CP_COMMIT();

    auto ldchunk = [&](int kv0, int s) {
        const uint32_t st = sb + s * AST;
        const uint32_t so = row * GRS + seg * 32;
        const __nv_bfloat16* pkh = khi + (size_t)(kv0 + row) * D + h * HD + seg * 16;
        const __nv_bfloat16* pkl = klo + (size_t)(kv0 + row) * D + h * HD + seg * 16;
        const __nv_bfloat16* pvh = vhi + (size_t)(kv0 + row) * D + h * HD + seg * 16;
        const __nv_bfloat16* pvl = vlo + (size_t)(kv0 + row) * D + h * HD + seg * 16;
        cpa16(st + A_KH + so, pkh);     cpa16(st + A_KH + so + 16, pkh + 8);
        cpa16(st + A_KL + so, pkl);     cpa16(st + A_KL + so + 16, pkl + 8);
        cpa16(st + A_VH + so, pvh);     cpa16(st + A_VH + so + 16, pvh + 8);
        cpa16(st + A_VL + so, pvl);     cpa16(st + A_VL + so + 16, pvl + 8);
    };

    ldchunk(0, 0);
    CP_COMMIT();

    CP_WAIT1();          // Q resident; chunk 0 may still be in flight
    __syncthreads();

    float oacc[8][4] = {};       // partial O for this warp's kv half
    float lsum0 = 0.f, lsum1 = 0.f;

    const int NCH = KVLEN / 128;  // 30
    for (int c = 0; c < NCH; c++) {
        if (c + 1 < NCH) {
            ldchunk((c + 1) * 128, (c + 1) & 1);
            CP_COMMIT();
            CP_WAIT1();
        } else {
            CP_WAIT0();
        }
        __syncthreads();
        const uint32_t st = sb + (c & 1) * AST;

        float sacc[8][4] = {};
        // S = q . k^T for this warp's 64-kv half (3-term split)
#pragma unroll
        for (int kt = 0; kt < 4; kt++) {
            uint32_t qH[4], qL[4];
            const uint32_t ar = (qw * 16 + lrow) * GRS + kt * 32 + lcolb;
            ldmx4(qH, sb + A_QH + ar);
            ldmx4(qL, sb + A_QL + ar);
#pragma unroll
            for (int nfp = 0; nfp < 4; nfp++) {
                uint32_t r[4], s[4];
                const uint32_t br =
                    (kw * 64 + nfp * 16 + lrow) * GRS + kt * 32 + lcolb;
                ldmx4(r, st + A_KH + br);
                ldmx4(s, st + A_KL + br);
                mma_bf16(sacc[2 * nfp], qH, r[0], r[2]);
                mma_bf16(sacc[2 * nfp + 1], qH, r[1], r[3]);
                mma_bf16(sacc[2 * nfp], qH, s[0], s[2]);
                mma_bf16(sacc[2 * nfp + 1], qH, s[1], s[3]);
                mma_bf16(sacc[2 * nfp], qL, r[0], r[2]);
                mma_bf16(sacc[2 * nfp + 1], qL, r[1], r[3]);
            }
        }
        // p = exp2(S') -> P fragments (hi/lo) -> partial O += P . V
#pragma unroll
        for (int kt2 = 0; kt2 < 4; kt2++) {
            const float* s0 = sacc[2 * kt2];
            const float* s1 = sacc[2 * kt2 + 1];
            float p0 = exp2f(s0[0]), p1 = exp2f(s0[1]);
            float p2 = exp2f(s0[2]), p3 = exp2f(s0[3]);
            float p4 = exp2f(s1[0]), p5 = exp2f(s1[1]);
            float p6 = exp2f(s1[2]), p7 = exp2f(s1[3]);
            lsum0 += p0 + p1 + p4 + p5;
            lsum1 += p2 + p3 + p6 + p7;
            __nv_bfloat16 h0, l0, h1, l1, h2, l2, h3, l3;
            __nv_bfloat16 h4, l4, h5, l5, h6, l6, h7, l7;
            split2(p0, h0, l0); split2(p1, h1, l1);
            split2(p2, h2, l2); split2(p3, h3, l3);
            split2(p4, h4, l4); split2(p5, h5, l5);
            split2(p6, h6, l6); split2(p7, h7, l7);
            uint32_t aPH[4] = {pack2(h0, h1), pack2(h2, h3), pack2(h4, h5), pack2(h6, h7)};
            uint32_t aPL[4] = {pack2(l0, l1), pack2(l2, l3), pack2(l4, l5), pack2(l6, l7)};
            // V rows for this slice: kw*64 + kt2*16
            const int vr0 = (kw * 4 + kt2) * 16 + ((lane >> 4) << 3) + (lane & 7);
            const uint32_t vcb = ((lane & 8) << 1);
#pragma unroll
            for (int df = 0; df < 4; df++) {
                uint32_t r[4], s[4];
                const uint32_t br = vr0 * GRS + df * 32 + vcb;
                ldmx4t(r, st + A_VH + br);
                ldmx4t(s, st + A_VL + br);
                mma_bf16(oacc[2 * df], aPH, r[0], r[2]);
                mma_bf16(oacc[2 * df + 1], aPH, r[1], r[3]);
                mma_bf16(oacc[2 * df], aPH, s[0], s[2]);
                mma_bf16(oacc[2 * df + 1], aPH, s[1], s[3]);
                mma_bf16(oacc[2 * df], aPL, r[0], r[2]);
                mma_bf16(oacc[2 * df + 1], aPL, r[1], r[3]);
            }
        }
        __syncthreads();
    }

    // reduce the two kv-half partials through smem (stage area is free now)
    float* red = (float*)sm;
    if (kw == 1) {
        float* dst = red + (qw * 32 + lane) * 34;
#pragma unroll
        for (int df = 0; df < 8; df++)
#pragma unroll
            for (int j = 0; j < 4; j++) dst[df * 4 + j] = oacc[df][j];
        dst[32] = lsum0;
        dst[33] = lsum1;
    }
    __syncthreads();
    if (kw == 0) {
        const float* src = red + (qw * 32 + lane) * 34;
#pragma unroll
        for (int df = 0; df < 8; df++)
#pragma unroll
            for (int j = 0; j < 4; j++) oacc[df][j] += src[df * 4 + j];
        lsum0 += src[32];
        lsum1 += src[33];

        // reduce row sums across the 4 lanes of each quad
#pragma unroll
        for (int off = 1; off <= 2; off <<= 1) {
            lsum0 += __shfl_xor_sync(0xffffffffu, lsum0, off);
            lsum1 += __shfl_xor_sync(0xffffffffu, lsum1, off);
        }
        const float inv0 = 1.0f / lsum0, inv1 = 1.0f / lsum1;

        const int g = lane >> 2, tq = lane & 3;
        const int r0 = q0 + qw * 16 + g, r1 = r0 + 8;
#pragma unroll
        for (int df = 0; df < 8; df++) {
            const int col = df * 8 + 2 * tq;
            __nv_bfloat16 h0, l0, h1, l1;
            split2(oacc[df][0] * inv0, h0, l0); split2(oacc[df][1] * inv0, h1, l1);
            *(uint32_t*)(ahi + (size_t)r0 * D + h * HD + col) = pack2(h0, h1);
            *(uint32_t*)(alo + (size_t)r0 * D + h * HD + col) = pack2(l0, l1);
            split2(oacc[df][2] * inv1, h0, l0); split2(oacc[df][3] * inv1, h1, l1);
            *(uint32_t*)(ahi + (size_t)r1 * D + h * HD + col) = pack2(h0, h1);
            *(uint32_t*)(alo + (size_t)r1 * D + h * HD + col) = pack2(l0, l1);
        }
    }
}

// ---------------------------------------------------------------------------
extern "C" void kernel_launch(void* const* d_in, const int* in_sizes, int n_in,
                              void* d_out, int out_size) {
    const float* ut  = (const float*)d_in[0];
    const float* rc  = (const float*)d_in[1];
    const float* mem = (const float*)d_in[2];
    const float* lck = (const float*)d_in[3];
    const float* lcv = (const float*)d_in[4];
    const float* Wq  = (const float*)d_in[5];
    const float* bq  = (const float*)d_in[6];
    const float* Wkv = (const float*)d_in[7];
    const float* bkv = (const float*)d_in[8];
    const float* Wo  = (const float*)d_in[9];
    const float* bo  = (const float*)d_in[10];

    float* out  = (float*)d_out;
    float* keyb = out + KEY_OFF;
    float* valb = out + VAL_OFF;

    __nv_bfloat16 *qih, *qil, *kvh, *kvl, *wqh, *wql, *wkh, *wkl, *woh, *wol;
    __nv_bfloat16 *qh, *ql, *kh, *kl, *vh, *vl, *ath, *atl;
    cudaGetSymbolAddress((void**)&qih, g_qin_hi);  cudaGetSymbolAddress((void**)&qil, g_qin_lo);
    cudaGetSymbolAddress((void**)&kvh, g_kvin_hi); cudaGetSymbolAddress((void**)&kvl, g_kvin_lo);
    cudaGetSymbolAddress((void**)&wqh, g_wq_hi);   cudaGetSymbolAddress((void**)&wql, g_wq_lo);
    cudaGetSymbolAddress((void**)&wkh, g_wkv_hi);  cudaGetSymbolAddress((void**)&wkl, g_wkv_lo);
    cudaGetSymbolAddress((void**)&woh, g_wo_hi);   cudaGetSymbolAddress((void**)&wol, g_wo_lo);
    cudaGetSymbolAddress((void**)&qh, g_q_hi);     cudaGetSymbolAddress((void**)&ql, g_q_lo);
    cudaGetSymbolAddress((void**)&kh, g_k_hi);     cudaGetSymbolAddress((void**)&kl, g_k_lo);
    cudaGetSymbolAddress((void**)&vh, g_v_hi);     cudaGetSymbolAddress((void**)&vl, g_v_lo);
    cudaGetSymbolAddress((void**)&ath, g_at_hi);   cudaGetSymbolAddress((void**)&atl, g_at_lo);

    cudaFuncSetAttribute(gemm_mma, cudaFuncAttributeMaxDynamicSharedMemorySize, GEMM_SMEM);
    cudaFuncSetAttribute(attn_mma, cudaFuncAttributeMaxDynamicSharedMemorySize, ATT_SMEM);

    // launch 0: weights
    conv_w<<<dim3(2048, 3), 256>>>(Wq, Wkv, Wo, wqh, wql, wkh, wkl, woh, wol);
    // launch 1: activations
    conv_act<<<dim3(2048, 5), 256>>>(rc, ut, mem, qih, qil, kvh, kvl);
    // launch 2: left-context
    conv_lc<<<(L_LEN * D) / 256, 256>>>(lck, lcv, keyb, valb, kh, kl, vh, vl);

    // launch 3: q = (q_in @ Wq^T + bq) * 0.125*log2e -> hi/lo
    gemm_mma<<<dim3(D / 128, QLEN / 128), 512, GEMM_SMEM>>>(
        qih, qil, wqh, wql, bq, D, D, 1,
        nullptr, nullptr, qh, ql, nullptr, nullptr);
    // launch 4: kv = kv_in @ Wkv^T + bkv -> key/value fp32 in d_out (+L-shift) + hi/lo
    gemm_mma<<<dim3(2 * D / 128, KVIN / 128), 512, GEMM_SMEM>>>(
        kvh, kvl, wkh, wkl, bkv, D, 2 * D, 2,
        keyb, valb, kh, kl, vh, vl);
    // launch 5 (ncu -s 5 target): attention -> attn hi/lo
    attn_mma<<<dim3(QLEN / 128, NH), 512, ATT_SMEM>>>(
        qh, ql, kh, kl, vh, vl, ath, atl);
    // launch 6: out = attn @ Wo^T + bo
    gemm_mma<<<dim3(D / 128, QLEN / 128), 512, GEMM_SMEM>>>(
        ath, atl, woh, wol, bo, D, D, 0,
        out, nullptr, nullptr, nullptr, nullptr, nullptr);
}

// round 14
// speedup vs baseline: 1.2420x; 1.0045x over previous
#include <cuda_runtime.h>
#include <cuda_bf16.h>
#include <cstdint>

#define D 1024
#define NH 16
#define HD 64
#define U_LEN 2048
#define R_LEN 256
#define L_LEN 1024
#define M_LEN 512
#define QLEN 2304   // U + R
#define KVLEN 3840  // M + R + L + U
#define KVIN 2816   // M + R + U
#define MR 768      // M + R

#define KEY_OFF (QLEN * D)
#define VAL_OFF (KEY_OFF + KVLEN * D)

#define SCALE_LOG2E 0.1803368801111204f   // 0.125 * log2(e)

// ---------------- scratch (allocation-free rule: __device__ globals) --------
__device__ __nv_bfloat16 g_qin_hi[QLEN * D], g_qin_lo[QLEN * D];
__device__ __nv_bfloat16 g_kvin_hi[KVIN * D], g_kvin_lo[KVIN * D];
__device__ __nv_bfloat16 g_wq_hi[D * D], g_wq_lo[D * D];
__device__ __nv_bfloat16 g_wkv_hi[2 * D * D], g_wkv_lo[2 * D * D];
__device__ __nv_bfloat16 g_wo_hi[D * D], g_wo_lo[D * D];
__device__ __nv_bfloat16 g_q_hi[QLEN * D], g_q_lo[QLEN * D];   // q * 0.125*log2e
__device__ __nv_bfloat16 g_k_hi[KVLEN * D], g_k_lo[KVLEN * D];
__device__ __nv_bfloat16 g_v_hi[KVLEN * D], g_v_lo[KVLEN * D];
__device__ __nv_bfloat16 g_at_hi[QLEN * D], g_at_lo[QLEN * D];

// ---------------- helpers ---------------------------------------------------
static __device__ __forceinline__ uint32_t s2u(const void* p) {
    uint32_t a;
    asm("{ .reg .u64 t; cvta.to.shared.u64 t, %1; cvt.u32.u64 %0, t; }"
        : "=r"(a) : "l"(p));
    return a;
}

static __device__ __forceinline__ void ldmx4(uint32_t* r, uint32_t addr) {
    asm volatile("ldmatrix.sync.aligned.m8n8.x4.shared.b16 {%0,%1,%2,%3}, [%4];"
                 : "=r"(r[0]), "=r"(r[1]), "=r"(r[2]), "=r"(r[3]) : "r"(addr));
}
static __device__ __forceinline__ void ldmx4t(uint32_t* r, uint32_t addr) {
    asm volatile("ldmatrix.sync.aligned.m8n8.x4.trans.shared.b16 {%0,%1,%2,%3}, [%4];"
                 : "=r"(r[0]), "=r"(r[1]), "=r"(r[2]), "=r"(r[3]) : "r"(addr));
}

static __device__ __forceinline__ void mma_bf16(float* c, const uint32_t* a,
                                                uint32_t b0, uint32_t b1) {
    asm volatile("mma.sync.aligned.m16n8k16.row.col.f32.bf16.bf16.f32 "
                 "{%0,%1,%2,%3}, {%4,%5,%6,%7}, {%8,%9}, {%0,%1,%2,%3};"
                 : "+f"(c[0]), "+f"(c[1]), "+f"(c[2]), "+f"(c[3])
                 : "r"(a[0]), "r"(a[1]), "r"(a[2]), "r"(a[3]), "r"(b0), "r"(b1));
}

static __device__ __forceinline__ void cpa16(uint32_t s, const void* g) {
    asm volatile("cp.async.cg.shared.global [%0], [%1], 16;" :: "r"(s), "l"(g));
}
#define CP_COMMIT() asm volatile("cp.async.commit_group;" ::: "memory")
#define CP_WAIT2() asm volatile("cp.async.wait_group 2;" ::: "memory")
#define CP_WAIT1() asm volatile("cp.async.wait_group 1;" ::: "memory")
#define CP_WAIT0() asm volatile("cp.async.wait_group 0;" ::: "memory")

static __device__ __forceinline__ uint32_t pack2(__nv_bfloat16 a, __nv_bfloat16 b) {
    uint16_t ua = *(uint16_t*)&a, ub = *(uint16_t*)&b;
    return (uint32_t)ua | ((uint32_t)ub << 16);
}
static __device__ __forceinline__ void split2(float x, __nv_bfloat16& h, __nv_bfloat16& l) {
    h = __float2bfloat16(x);
    l = __float2bfloat16(x - __bfloat162float(h));
}
// Fast pair split: hi = truncate-to-bf16 (exact, one PRMT for the packed pair),
// lo = x - hi (exact FSUB), packed with one cvt.rn.bf16x2.
// |lo| <= 2^-8 |x|; dropped lo*lo product term <= 2^-16 relative (OK).
static __device__ __forceinline__ void fsplit2(float x0, float x1,
                                               uint32_t& hi01, uint32_t& lo01) {
    const uint32_t u0 = __float_as_uint(x0), u1 = __float_as_uint(x1);
    hi01 = __byte_perm(u0, u1, 0x7632);   // [hi16(x0) | hi16(x1)<<16]
    const float l0 = x0 - __uint_as_float(u0 & 0xFFFF0000u);
    const float l1 = x1 - __uint_as_float(u1 & 0xFFFF0000u);
    asm("cvt.rn.bf16x2.f32 %0, %1, %2;" : "=r"(lo01) : "f"(l1), "f"(l0));
}

// ---------------- batched conversion kernels ---------------------------------
static __device__ __forceinline__ void conv_seg(const float* __restrict__ s,
                                                __nv_bfloat16* __restrict__ hi,
                                                __nv_bfloat16* __restrict__ lo,
                                                int n4, int i) {
    if (i >= n4) return;
    float4 v = ((const float4*)s)[i];
    uint32_t h01, l01, h23, l23;
    fsplit2(v.x, v.y, h01, l01);
    fsplit2(v.z, v.w, h23, l23);
    ((uint32_t*)hi)[2 * i] = h01;
    ((uint32_t*)hi)[2 * i + 1] = h23;
    ((uint32_t*)lo)[2 * i] = l01;
    ((uint32_t*)lo)[2 * i + 1] = l23;
}

__global__ void conv_w(const float* __restrict__ Wq, const float* __restrict__ Wkv,
                       const float* __restrict__ Wo,
                       __nv_bfloat16* wqh, __nv_bfloat16* wql,
                       __nv_bfloat16* wkh, __nv_bfloat16* wkl,
                       __nv_bfloat16* woh, __nv_bfloat16* wol) {
    const int i = blockIdx.x * blockDim.x + threadIdx.x;
    switch (blockIdx.y) {
        case 0: conv_seg(Wq, wqh, wql, D * D / 4, i); break;
        case 1: conv_seg(Wkv, wkh, wkl, 2 * D * D / 4, i); break;
        default: conv_seg(Wo, woh, wol, D * D / 4, i); break;
    }
}

__global__ void conv_act(const float* __restrict__ rc, const float* __restrict__ ut,
                         const float* __restrict__ mem,
                         __nv_bfloat16* qih, __nv_bfloat16* qil,
                         __nv_bfloat16* kvh, __nv_bfloat16* kvl) {
    const int i = blockIdx.x * blockDim.x + threadIdx.x;
    switch (blockIdx.y) {
        case 0: conv_seg(rc, qih, qil, R_LEN * D / 4, i); break;
        case 1: conv_seg(ut, qih + (size_t)R_LEN * D, qil + (size_t)R_LEN * D,
                         U_LEN * D / 4, i); break;
        case 2: conv_seg(mem, kvh, kvl, M_LEN * D / 4, i); break;
        case 3: conv_seg(rc, kvh + (size_t)M_LEN * D, kvl + (size_t)M_LEN * D,
                         R_LEN * D / 4, i); break;
        default: conv_seg(ut, kvh + (size_t)MR * D, kvl + (size_t)MR * D,
                          U_LEN * D / 4, i); break;
    }
}

__global__ void conv_lc(const float* __restrict__ lck, const float* __restrict__ lcv,
                        float* __restrict__ keyb, float* __restrict__ valb,
                        __nv_bfloat16* __restrict__ khi, __nv_bfloat16* __restrict__ klo,
                        __nv_bfloat16* __restrict__ vhi, __nv_bfloat16* __restrict__ vlo) {
    int i = blockIdx.x * blockDim.x + threadIdx.x;  // 0 .. L*D-1
    int r = i >> 10, c = i & 1023;
    float kv = lck[i], vv = lcv[i];
    size_t o = (size_t)(MR + r) * D + c;
    keyb[o] = kv;
    valb[o] = vv;
    __nv_bfloat16 h, l;
    split2(kv, h, l); khi[o] = h; klo[o] = l;
    split2(vv, h, l); vhi[o] = h; vlo[o] = l;
}

// ---------------- split-bf16 mma.sync GEMM (512 thr, 3-stage cp.async) -------
// C[M,N] = (Ahi+Alo)[M,K] @ (Bhi+Blo)[N,K]^T + bias (3-term split).
// Block tile 128x128, 16 warps 4x4 (warp tile 32x32); K-chunks of 64;
// smem rows 144B; 3 pipeline stages (216KB).
#define GRS 144
#define GST 73728                 // stage size: 4 tensors * 128 * 144
#define G_AH 0
#define G_AL 18432
#define G_BH 36864
#define G_BL 55296
#define GEMM_SMEM (3 * GST)

__global__ void __launch_bounds__(512, 1) gemm_mma(
    const __nv_bfloat16* __restrict__ Ahi, const __nv_bfloat16* __restrict__ Alo,
    const __nv_bfloat16* __restrict__ Bhi, const __nv_bfloat16* __restrict__ Blo,
    const float* __restrict__ bias, int K, int N, int mode,
    float* __restrict__ f32A, float* __restrict__ f32B,
    __nv_bfloat16* __restrict__ bhA, __nv_bfloat16* __restrict__ blA,
    __nv_bfloat16* __restrict__ bhB, __nv_bfloat16* __restrict__ blB) {
    extern __shared__ char sm[];
    const uint32_t sb = s2u(sm);
    const int tid = threadIdx.x;
    const int lane = tid & 31, wid = tid >> 5;
    const int wm = wid >> 2, wn = wid & 3;
    const int m0 = blockIdx.y * 128, n0 = blockIdx.x * 128;
    const int lrow = lane & 15;
    const int lcolb = (lane >> 4) * 16;
    const int row = tid >> 2, seg = tid & 3;   // loader: 128 rows x 4 segs of 32B

    float acc[2][4][4] = {};

    auto ldchunk = [&](int c, int s) {
        const int k0 = c << 6;
        const uint32_t st = sb + s * GST;
        const uint32_t so = row * GRS + seg * 32;
        const __nv_bfloat16* ga = Ahi + (size_t)(m0 + row) * K + k0 + seg * 16;
        const __nv_bfloat16* gb = Alo + (size_t)(m0 + row) * K + k0 + seg * 16;
        const __nv_bfloat16* gc = Bhi + (size_t)(n0 + row) * K + k0 + seg * 16;
        const __nv_bfloat16* gd = Blo + (size_t)(n0 + row) * K + k0 + seg * 16;
        cpa16(st + G_AH + so, ga);       cpa16(st + G_AH + so + 16, ga + 8);
        cpa16(st + G_AL + so, gb);       cpa16(st + G_AL + so + 16, gb + 8);
        cpa16(st + G_BH + so, gc);       cpa16(st + G_BH + so + 16, gc + 8);
        cpa16(st + G_BL + so, gd);       cpa16(st + G_BL + so + 16, gd + 8);
    };

    const int nch = K >> 6;
    ldchunk(0, 0);
    CP_COMMIT();
    if (nch > 1) { ldchunk(1, 1); CP_COMMIT(); }

    for (int c = 0; c < nch; c++) {
        if (c + 2 < nch) {
            ldchunk(c + 2, (c + 2) % 3);
            CP_COMMIT();
            CP_WAIT2();
        } else if (c + 1 < nch) {
            CP_WAIT1();
        } else {
            CP_WAIT0();
        }
        __syncthreads();
        const uint32_t st = sb + (c % 3) * GST;
#pragma unroll
        for (int kt = 0; kt < 4; kt++) {
            uint32_t aH[2][4], aL[2][4];
#pragma unroll
            for (int mf = 0; mf < 2; mf++) {
                const uint32_t ar = (wm * 32 + mf * 16 + lrow) * GRS + kt * 32 + lcolb;
                ldmx4(aH[mf], st + G_AH + ar);
                ldmx4(aL[mf], st + G_AL + ar);
            }
#pragma unroll
            for (int nfp = 0; nfp < 2; nfp++) {
                uint32_t r[4], s[4];
                const uint32_t br = (wn * 32 + nfp * 16 + lrow) * GRS + kt * 32 + lcolb;
                ldmx4(r, st + G_BH + br);
                ldmx4(s, st + G_BL + br);
#pragma unroll
                for (int mf = 0; mf < 2; mf++) {
                    mma_bf16(acc[mf][2 * nfp], aH[mf], r[0], r[2]);
                    mma_bf16(acc[mf][2 * nfp + 1], aH[mf], r[1], r[3]);
                    mma_bf16(acc[mf][2 * nfp], aH[mf], s[0], s[2]);
                    mma_bf16(acc[mf][2 * nfp + 1], aH[mf], s[1], s[3]);
                    mma_bf16(acc[mf][2 * nfp], aL[mf], r[0], r[2]);
                    mma_bf16(acc[mf][2 * nfp + 1], aL[mf], r[1], r[3]);
                }
            }
        }
        __syncthreads();
    }

    // epilogue
    const int g = lane >> 2, tq = lane & 3;
#pragma unroll
    for (int mf = 0; mf < 2; mf++) {
        const int r0 = m0 + wm * 32 + mf * 16 + g;
        const int r1 = r0 + 8;
#pragma unroll
        for (int nf = 0; nf < 4; nf++) {
            const int col = n0 + wn * 32 + nf * 8 + 2 * tq;
            const float b0 = bias[col], b1 = bias[col + 1];
            float v0 = acc[mf][nf][0] + b0, v1 = acc[mf][nf][1] + b1;
            float v2 = acc[mf][nf][2] + b0, v3 = acc[mf][nf][3] + b1;
            if (mode == 0) {
                *(float2*)(f32A + (size_t)r0 * N + col) = {v0, v1};
                *(float2*)(f32A + (size_t)r1 * N + col) = {v2, v3};
            } else if (mode == 1) {
                uint32_t h01, l01;
                fsplit2(v0 * SCALE_LOG2E, v1 * SCALE_LOG2E, h01, l01);
                *(uint32_t*)(bhA + (size_t)r0 * N + col) = h01;
                *(uint32_t*)(blA + (size_t)r0 * N + col) = l01;
                fsplit2(v2 * SCALE_LOG2E, v3 * SCALE_LOG2E, h01, l01);
                *(uint32_t*)(bhA + (size_t)r1 * N + col) = h01;
                *(uint32_t*)(blA + (size_t)r1 * N + col) = l01;
            } else {
                const int d0 = (r0 < MR) ? r0 : r0 + L_LEN;
                const int d1 = (r1 < MR) ? r1 : r1 + L_LEN;
                float* fdst;
                __nv_bfloat16 *hdst, *ldst;
                int cc;
                if (col < D) { fdst = f32A; hdst = bhA; ldst = blA; cc = col; }
                else         { fdst = f32B; hdst = bhB; ldst = blB; cc = col - D; }
                *(float2*)(fdst + (size_t)d0 * D + cc) = {v0, v1};
                *(float2*)(fdst + (size_t)d1 * D + cc) = {v2, v3};
                uint32_t h01, l01;
                fsplit2(v0, v1, h01, l01);
                *(uint32_t*)(hdst + (size_t)d0 * D + cc) = h01;
                *(uint32_t*)(ldst + (size_t)d0 * D + cc) = l01;
                fsplit2(v2, v3, h01, l01);
                *(uint32_t*)(hdst + (size_t)d1 * D + cc) = h01;
                *(uint32_t*)(ldst + (size_t)d1 * D + cc) = l01;
            }
        }
    }
}

// ---------------- mma.sync flash attention (512 thr, kv-split warps) ---------
// grid (QLEN/128, NH). 16 warps = 8 q-groups x 2 kv-halves. KV chunks of 128;
// each warp computes S and partial O for its 64-kv half; partials accumulate
// in registers across all chunks; one smem reduction at the end.
#define A_KH 0
#define A_KL 18432
#define A_VH 36864
#define A_VL 55296
#define AST 73728                  // stage size
#define A_QH (2 * AST)
#define A_QL (2 * AST + 18432)
#define ATT_SMEM (2 * AST + 36864)

__global__ void __launch_bounds__(512, 1) attn_mma(
    const __nv_bfloat16* __restrict__ qhi, const __nv_bfloat16* __restrict__ qlo,
    const __nv_bfloat16* __restrict__ khi, const __nv_bfloat16* __restrict__ klo,
    const __nv_bfloat16* __restrict__ vhi, const __nv_bfloat16* __restrict__ vlo,
    __nv_bfloat16* __restrict__ ahi, __nv_bfloat16* __restrict__ alo) {
    extern __shared__ char sm[];
    const uint32_t sb = s2u(sm);
    const int tid = threadIdx.x;
    const int lane = tid & 31, wid = tid >> 5;
    const int qw = wid >> 1, kw = wid & 1;   // q-group 0..7, kv-half 0..1
    const int h = blockIdx.y;
    const int q0 = blockIdx.x * 128;
    const int lrow = lane & 15;
    const int lcolb = (lane >> 4) * 16;
    const int row = tid >> 2, seg = tid & 3;

    // Q tile via cp.async (group 0): 2 tensors, 128 rows x 128B
    {
        const uint32_t so = row * GRS + seg * 32;
        const __nv_bfloat16* ph = qhi + (size_t)(q0 + row) * D + h * HD + seg * 16;
        const __nv_bfloat16* pl = qlo + (size_t)(q0 + row) * D + h * HD + seg * 16;
        cpa16(sb + A_QH + so, ph);      cpa16(sb + A_QH + so + 16, ph + 8);
        cpa16(sb + A_QL + so, pl);      cpa16(sb + A_QL + so + 16, pl + 8);
    }
    CP_COMMIT();

    auto ldchunk = [&](int kv0, int s) {
        const uint32_t st = sb + s * AST;
        const uint32_t so = row * GRS + seg * 32;
        const __nv_bfloat16* pkh = khi + (size_t)(kv0 + row) * D + h * HD + seg * 16;
        const __nv_bfloat16* pkl = klo + (size_t)(kv0 + row) * D + h * HD + seg * 16;
        const __nv_bfloat16* pvh = vhi + (size_t)(kv0 + row) * D + h * HD + seg * 16;
        const __nv_bfloat16* pvl = vlo + (size_t)(kv0 + row) * D + h * HD + seg * 16;
        cpa16(st + A_KH + so, pkh);     cpa16(st + A_KH + so + 16, pkh + 8);
        cpa16(st + A_KL + so, pkl);     cpa16(st + A_KL + so + 16, pkl + 8);
        cpa16(st + A_VH + so, pvh);     cpa16(st + A_VH + so + 16, pvh + 8);
        cpa16(st + A_VL + so, pvl);     cpa16(st + A_VL + so + 16, pvl + 8);
    };

    ldchunk(0, 0);
    CP_COMMIT();

    CP_WAIT1();          // Q resident; chunk 0 may still be in flight
    __syncthreads();

    float oacc[8][4] = {};       // partial O for this warp's kv half
    float lsum0 = 0.f, lsum1 = 0.f;

    const int NCH = KVLEN / 128;  // 30
    for (int c = 0; c < NCH; c++) {
        if (c + 1 < NCH) {
            ldchunk((c + 1) * 128, (c + 1) & 1);
            CP_COMMIT();
            CP_WAIT1();
        } else {
            CP_WAIT0();
        }
        __syncthreads();
        const uint32_t st = sb + (c & 1) * AST;

        float sacc[8][4] = {};
        // S = q . k^T for this warp's 64-kv half (3-term split)
#pragma unroll
        for (int kt = 0; kt < 4; kt++) {
            uint32_t qH[4], qL[4];
            const uint32_t ar = (qw * 16 + lrow) * GRS + kt * 32 + lcolb;
            ldmx4(qH, sb + A_QH + ar);
            ldmx4(qL, sb + A_QL + ar);
#pragma unroll
            for (int nfp = 0; nfp < 4; nfp++) {
                uint32_t r[4], s[4];
                const uint32_t br =
                    (kw * 64 + nfp * 16 + lrow) * GRS + kt * 32 + lcolb;
                ldmx4(r, st + A_KH + br);
                ldmx4(s, st + A_KL + br);
                mma_bf16(sacc[2 * nfp], qH, r[0], r[2]);
                mma_bf16(sacc[2 * nfp + 1], qH, r[1], r[3]);
                mma_bf16(sacc[2 * nfp], qH, s[0], s[2]);
                mma_bf16(sacc[2 * nfp + 1], qH, s[1], s[3]);
                mma_bf16(sacc[2 * nfp], qL, r[0], r[2]);
                mma_bf16(sacc[2 * nfp + 1], qL, r[1], r[3]);
            }
        }
        // p = exp2(S') -> P fragments (hi/lo) -> partial O += P . V
#pragma unroll
        for (int kt2 = 0; kt2 < 4; kt2++) {
            const float* s0 = sacc[2 * kt2];
            const float* s1 = sacc[2 * kt2 + 1];
            float p0 = exp2f(s0[0]), p1 = exp2f(s0[1]);
            float p2 = exp2f(s0[2]), p3 = exp2f(s0[3]);
            float p4 = exp2f(s1[0]), p5 = exp2f(s1[1]);
            float p6 = exp2f(s1[2]), p7 = exp2f(s1[3]);
            lsum0 += p0 + p1 + p4 + p5;
            lsum1 += p2 + p3 + p6 + p7;
            uint32_t aPH[4], aPL[4];
            fsplit2(p0, p1, aPH[0], aPL[0]);
            fsplit2(p2, p3, aPH[1], aPL[1]);
            fsplit2(p4, p5, aPH[2], aPL[2]);
            fsplit2(p6, p7, aPH[3], aPL[3]);
            // V rows for this slice: kw*64 + kt2*16
            const int vr0 = (kw * 4 + kt2) * 16 + ((lane >> 4) << 3) + (lane & 7);
            const uint32_t vcb = ((lane & 8) << 1);
#pragma unroll
            for (int df = 0; df < 4; df++) {
                uint32_t r[4], s[4];
                const uint32_t br = vr0 * GRS + df * 32 + vcb;
                ldmx4t(r, st + A_VH + br);
                ldmx4t(s, st + A_VL + br);
                mma_bf16(oacc[2 * df], aPH, r[0], r[2]);
                mma_bf16(oacc[2 * df + 1], aPH, r[1], r[3]);
                mma_bf16(oacc[2 * df], aPH, s[0], s[2]);
                mma_bf16(oacc[2 * df + 1], aPH, s[1], s[3]);
                mma_bf16(oacc[2 * df], aPL, r[0], r[2]);
                mma_bf16(oacc[2 * df + 1], aPL, r[1], r[3]);
            }
        }
        __syncthreads();
    }

    // reduce the two kv-half partials through smem (stage area is free now)
    float* red = (float*)sm;
    if (kw == 1) {
        float* dst = red + (qw * 32 + lane) * 34;
#pragma unroll
        for (int df = 0; df < 8; df++)
#pragma unroll
            for (int j = 0; j < 4; j++) dst[df * 4 + j] = oacc[df][j];
        dst[32] = lsum0;
        dst[33] = lsum1;
    }
    __syncthreads();
    if (kw == 0) {
        const float* src = red + (qw * 32 + lane) * 34;
#pragma unroll
        for (int df = 0; df < 8; df++)
#pragma unroll
            for (int j = 0; j < 4; j++) oacc[df][j] += src[df * 4 + j];
        lsum0 += src[32];
        lsum1 += src[33];

        // reduce row sums across the 4 lanes of each quad
#pragma unroll
        for (int off = 1; off <= 2; off <<= 1) {
            lsum0 += __shfl_xor_sync(0xffffffffu, lsum0, off);
            lsum1 += __shfl_xor_sync(0xffffffffu, lsum1, off);
        }
        const float inv0 = 1.0f / lsum0, inv1 = 1.0f / lsum1;

        const int g = lane >> 2, tq = lane & 3;
        const int r0 = q0 + qw * 16 + g, r1 = r0 + 8;
#pragma unroll
        for (int df = 0; df < 8; df++) {
            const int col = df * 8 + 2 * tq;
            uint32_t h01, l01;
            fsplit2(oacc[df][0] * inv0, oacc[df][1] * inv0, h01, l01);
            *(uint32_t*)(ahi + (size_t)r0 * D + h * HD + col) = h01;
            *(uint32_t*)(alo + (size_t)r0 * D + h * HD + col) = l01;
            fsplit2(oacc[df][2] * inv1, oacc[df][3] * inv1, h01, l01);
            *(uint32_t*)(ahi + (size_t)r1 * D + h * HD + col) = h01;
            *(uint32_t*)(alo + (size_t)r1 * D + h * HD + col) = l01;
        }
    }
}

// ---------------------------------------------------------------------------
extern "C" void kernel_launch(void* const* d_in, const int* in_sizes, int n_in,
                              void* d_out, int out_size) {
    const float* ut  = (const float*)d_in[0];
    const float* rc  = (const float*)d_in[1];
    const float* mem = (const float*)d_in[2];
    const float* lck = (const float*)d_in[3];
    const float* lcv = (const float*)d_in[4];
    const float* Wq  = (const float*)d_in[5];
    const float* bq  = (const float*)d_in[6];
    const float* Wkv = (const float*)d_in[7];
    const float* bkv = (const float*)d_in[8];
    const float* Wo  = (const float*)d_in[9];
    const float* bo  = (const float*)d_in[10];

    float* out  = (float*)d_out;
    float* keyb = out + KEY_OFF;
    float* valb = out + VAL_OFF;

    __nv_bfloat16 *qih, *qil, *kvh, *kvl, *wqh, *wql, *wkh, *wkl, *woh, *wol;
    __nv_bfloat16 *qh, *ql, *kh, *kl, *vh, *vl, *ath, *atl;
    cudaGetSymbolAddress((void**)&qih, g_qin_hi);  cudaGetSymbolAddress((void**)&qil, g_qin_lo);
    cudaGetSymbolAddress((void**)&kvh, g_kvin_hi); cudaGetSymbolAddress((void**)&kvl, g_kvin_lo);
    cudaGetSymbolAddress((void**)&wqh, g_wq_hi);   cudaGetSymbolAddress((void**)&wql, g_wq_lo);
    cudaGetSymbolAddress((void**)&wkh, g_wkv_hi);  cudaGetSymbolAddress((void**)&wkl, g_wkv_lo);
    cudaGetSymbolAddress((void**)&woh, g_wo_hi);   cudaGetSymbolAddress((void**)&wol, g_wo_lo);
    cudaGetSymbolAddress((void**)&qh, g_q_hi);     cudaGetSymbolAddress((void**)&ql, g_q_lo);
    cudaGetSymbolAddress((void**)&kh, g_k_hi);     cudaGetSymbolAddress((void**)&kl, g_k_lo);
    cudaGetSymbolAddress((void**)&vh, g_v_hi);     cudaGetSymbolAddress((void**)&vl, g_v_lo);
    cudaGetSymbolAddress((void**)&ath, g_at_hi);   cudaGetSymbolAddress((void**)&atl, g_at_lo);

    cudaFuncSetAttribute(gemm_mma, cudaFuncAttributeMaxDynamicSharedMemorySize, GEMM_SMEM);
    cudaFuncSetAttribute(attn_mma, cudaFuncAttributeMaxDynamicSharedMemorySize, ATT_SMEM);

    // launch 0: weights
    conv_w<<<dim3(2048, 3), 256>>>(Wq, Wkv, Wo, wqh, wql, wkh, wkl, woh, wol);
    // launch 1: activations
    conv_act<<<dim3(2048, 5), 256>>>(rc, ut, mem, qih, qil, kvh, kvl);
    // launch 2: left-context
    conv_lc<<<(L_LEN * D) / 256, 256>>>(lck, lcv, keyb, valb, kh, kl, vh, vl);

    // launch 3: q = (q_in @ Wq^T + bq) * 0.125*log2e -> hi/lo
    gemm_mma<<<dim3(D / 128, QLEN / 128), 512, GEMM_SMEM>>>(
        qih, qil, wqh, wql, bq, D, D, 1,
        nullptr, nullptr, qh, ql, nullptr, nullptr);
    // launch 4: kv = kv_in @ Wkv^T + bkv -> key/value fp32 in d_out (+L-shift) + hi/lo
    gemm_mma<<<dim3(2 * D / 128, KVIN / 128), 512, GEMM_SMEM>>>(
        kvh, kvl, wkh, wkl, bkv, D, 2 * D, 2,
        keyb, valb, kh, kl, vh, vl);
    // launch 5 (ncu -s 5 target): attention -> attn hi/lo
    attn_mma<<<dim3(QLEN / 128, NH), 512, ATT_SMEM>>>(
        qh, ql, kh, kl, vh, vl, ath, atl);
    // launch 6: out = attn @ Wo^T + bo
    gemm_mma<<<dim3(D / 128, QLEN / 128), 512, GEMM_SMEM>>>(
        ath, atl, woh, wol, bo, D, D, 0,
        out, nullptr, nullptr, nullptr, nullptr, nullptr);
}

// round 15
// speedup vs baseline: 1.4648x; 1.1794x over previous
#include <cuda_runtime.h>
#include <cuda_bf16.h>
#include <cuda_fp16.h>
#include <cstdint>

#define D 1024
#define NH 16
#define HD 64
#define U_LEN 2048
#define R_LEN 256
#define L_LEN 1024
#define M_LEN 512
#define QLEN 2304   // U + R
#define KVLEN 3840  // M + R + L + U
#define KVIN 2816   // M + R + U
#define MR 768      // M + R

#define KEY_OFF (QLEN * D)
#define VAL_OFF (KEY_OFF + KVLEN * D)

#define SCALE_LOG2E 0.1803368801111204f   // 0.125 * log2(e)

// ---------------- scratch (allocation-free rule: __device__ globals) --------
__device__ __nv_bfloat16 g_qin_hi[QLEN * D], g_qin_lo[QLEN * D];
__device__ __nv_bfloat16 g_kvin_hi[KVIN * D], g_kvin_lo[KVIN * D];
__device__ __nv_bfloat16 g_wq_hi[D * D], g_wq_lo[D * D];
__device__ __nv_bfloat16 g_wkv_hi[2 * D * D], g_wkv_lo[2 * D * D];
__device__ __nv_bfloat16 g_wo_hi[D * D], g_wo_lo[D * D];
__device__ __half       g_q_f16[QLEN * D];    // q * 0.125*log2e, fp16 single
__device__ __half       g_k_f16[KVLEN * D];   // key, fp16 single (attn use)
__device__ __nv_bfloat16 g_v_hi[KVLEN * D], g_v_lo[KVLEN * D];
__device__ __nv_bfloat16 g_at_hi[QLEN * D], g_at_lo[QLEN * D];

// ---------------- helpers ---------------------------------------------------
static __device__ __forceinline__ uint32_t s2u(const void* p) {
    uint32_t a;
    asm("{ .reg .u64 t; cvta.to.shared.u64 t, %1; cvt.u32.u64 %0, t; }"
        : "=r"(a) : "l"(p));
    return a;
}

static __device__ __forceinline__ void ldmx4(uint32_t* r, uint32_t addr) {
    asm volatile("ldmatrix.sync.aligned.m8n8.x4.shared.b16 {%0,%1,%2,%3}, [%4];"
                 : "=r"(r[0]), "=r"(r[1]), "=r"(r[2]), "=r"(r[3]) : "r"(addr));
}
static __device__ __forceinline__ void ldmx4t(uint32_t* r, uint32_t addr) {
    asm volatile("ldmatrix.sync.aligned.m8n8.x4.trans.shared.b16 {%0,%1,%2,%3}, [%4];"
                 : "=r"(r[0]), "=r"(r[1]), "=r"(r[2]), "=r"(r[3]) : "r"(addr));
}

static __device__ __forceinline__ void mma_bf16(float* c, const uint32_t* a,
                                                uint32_t b0, uint32_t b1) {
    asm volatile("mma.sync.aligned.m16n8k16.row.col.f32.bf16.bf16.f32 "
                 "{%0,%1,%2,%3}, {%4,%5,%6,%7}, {%8,%9}, {%0,%1,%2,%3};"
                 : "+f"(c[0]), "+f"(c[1]), "+f"(c[2]), "+f"(c[3])
                 : "r"(a[0]), "r"(a[1]), "r"(a[2]), "r"(a[3]), "r"(b0), "r"(b1));
}
static __device__ __forceinline__ void mma_f16(float* c, const uint32_t* a,
                                               uint32_t b0, uint32_t b1) {
    asm volatile("mma.sync.aligned.m16n8k16.row.col.f32.f16.f16.f32 "
                 "{%0,%1,%2,%3}, {%4,%5,%6,%7}, {%8,%9}, {%0,%1,%2,%3};"
                 : "+f"(c[0]), "+f"(c[1]), "+f"(c[2]), "+f"(c[3])
                 : "r"(a[0]), "r"(a[1]), "r"(a[2]), "r"(a[3]), "r"(b0), "r"(b1));
}

static __device__ __forceinline__ void cpa16(uint32_t s, const void* g) {
    asm volatile("cp.async.cg.shared.global [%0], [%1], 16;" :: "r"(s), "l"(g));
}
#define CP_COMMIT() asm volatile("cp.async.commit_group;" ::: "memory")
#define CP_WAIT2() asm volatile("cp.async.wait_group 2;" ::: "memory")
#define CP_WAIT1() asm volatile("cp.async.wait_group 1;" ::: "memory")
#define CP_WAIT0() asm volatile("cp.async.wait_group 0;" ::: "memory")

static __device__ __forceinline__ void split2(float x, __nv_bfloat16& h, __nv_bfloat16& l) {
    h = __float2bfloat16(x);
    l = __float2bfloat16(x - __bfloat162float(h));
}
// Fast pair split: hi = truncate-to-bf16 (one PRMT for the pair), lo = exact
// residual rounded to bf16x2 (one cvt). Dropped lo*lo term <= 2^-16 relative.
static __device__ __forceinline__ void fsplit2(float x0, float x1,
                                               uint32_t& hi01, uint32_t& lo01) {
    const uint32_t u0 = __float_as_uint(x0), u1 = __float_as_uint(x1);
    hi01 = __byte_perm(u0, u1, 0x7632);   // [hi16(x0) | hi16(x1)<<16]
    const float l0 = x0 - __uint_as_float(u0 & 0xFFFF0000u);
    const float l1 = x1 - __uint_as_float(u1 & 0xFFFF0000u);
    asm("cvt.rn.bf16x2.f32 %0, %1, %2;" : "=r"(lo01) : "f"(l1), "f"(l0));
}
static __device__ __forceinline__ uint32_t packh2(float a, float b) {
    __half2 h = __floats2half2_rn(a, b);
    return *(uint32_t*)&h;
}

// ---------------- batched conversion kernels ---------------------------------
static __device__ __forceinline__ void conv_seg(const float* __restrict__ s,
                                                __nv_bfloat16* __restrict__ hi,
                                                __nv_bfloat16* __restrict__ lo,
                                                int n4, int i) {
    if (i >= n4) return;
    float4 v = ((const float4*)s)[i];
    uint32_t h01, l01, h23, l23;
    fsplit2(v.x, v.y, h01, l01);
    fsplit2(v.z, v.w, h23, l23);
    ((uint32_t*)hi)[2 * i] = h01;
    ((uint32_t*)hi)[2 * i + 1] = h23;
    ((uint32_t*)lo)[2 * i] = l01;
    ((uint32_t*)lo)[2 * i + 1] = l23;
}

__global__ void conv_w(const float* __restrict__ Wq, const float* __restrict__ Wkv,
                       const float* __restrict__ Wo,
                       __nv_bfloat16* wqh, __nv_bfloat16* wql,
                       __nv_bfloat16* wkh, __nv_bfloat16* wkl,
                       __nv_bfloat16* woh, __nv_bfloat16* wol) {
    const int i = blockIdx.x * blockDim.x + threadIdx.x;
    switch (blockIdx.y) {
        case 0: conv_seg(Wq, wqh, wql, D * D / 4, i); break;
        case 1: conv_seg(Wkv, wkh, wkl, 2 * D * D / 4, i); break;
        default: conv_seg(Wo, woh, wol, D * D / 4, i); break;
    }
}

__global__ void conv_act(const float* __restrict__ rc, const float* __restrict__ ut,
                         const float* __restrict__ mem,
                         __nv_bfloat16* qih, __nv_bfloat16* qil,
                         __nv_bfloat16* kvh, __nv_bfloat16* kvl) {
    const int i = blockIdx.x * blockDim.x + threadIdx.x;
    switch (blockIdx.y) {
        case 0: conv_seg(rc, qih, qil, R_LEN * D / 4, i); break;
        case 1: conv_seg(ut, qih + (size_t)R_LEN * D, qil + (size_t)R_LEN * D,
                         U_LEN * D / 4, i); break;
        case 2: conv_seg(mem, kvh, kvl, M_LEN * D / 4, i); break;
        case 3: conv_seg(rc, kvh + (size_t)M_LEN * D, kvl + (size_t)M_LEN * D,
                         R_LEN * D / 4, i); break;
        default: conv_seg(ut, kvh + (size_t)MR * D, kvl + (size_t)MR * D,
                          U_LEN * D / 4, i); break;
    }
}

__global__ void conv_lc(const float* __restrict__ lck, const float* __restrict__ lcv,
                        float* __restrict__ keyb, float* __restrict__ valb,
                        __half* __restrict__ kf16,
                        __nv_bfloat16* __restrict__ vhi, __nv_bfloat16* __restrict__ vlo) {
    int i = blockIdx.x * blockDim.x + threadIdx.x;  // 0 .. L*D-1
    int r = i >> 10, c = i & 1023;
    float kv = lck[i], vv = lcv[i];
    size_t o = (size_t)(MR + r) * D + c;
    keyb[o] = kv;
    valb[o] = vv;
    kf16[o] = __float2half(kv);
    __nv_bfloat16 h, l;
    split2(vv, h, l); vhi[o] = h; vlo[o] = l;
}

// ---------------- split-bf16 mma.sync GEMM (512 thr, 3-stage cp.async) -------
// C[M,N] = (Ahi+Alo)[M,K] @ (Bhi+Blo)[N,K]^T + bias (3-term split).
// Block tile 128x128, 16 warps 4x4 (warp tile 32x32); K-chunks of 64.
// mode 0: fp32 out. mode 1: (acc+bias)*scale -> hA fp16 (q path).
// mode 2: KV: key half -> f32A(keyb) + hA fp16 with L-shift; value half ->
//         f32B(valb) + bf16 hi/lo bhB/blB.
#define GRS 144
#define GST 73728                 // stage size: 4 tensors * 128 * 144
#define G_AH 0
#define G_AL 18432
#define G_BH 36864
#define G_BL 55296
#define GEMM_SMEM (3 * GST)

__global__ void __launch_bounds__(512, 1) gemm_mma(
    const __nv_bfloat16* __restrict__ Ahi, const __nv_bfloat16* __restrict__ Alo,
    const __nv_bfloat16* __restrict__ Bhi, const __nv_bfloat16* __restrict__ Blo,
    const float* __restrict__ bias, int K, int N, int mode,
    float* __restrict__ f32A, float* __restrict__ f32B,
    __half* __restrict__ hA,
    __nv_bfloat16* __restrict__ bhB, __nv_bfloat16* __restrict__ blB) {
    extern __shared__ char sm[];
    const uint32_t sb = s2u(sm);
    const int tid = threadIdx.x;
    const int lane = tid & 31, wid = tid >> 5;
    const int wm = wid >> 2, wn = wid & 3;
    const int m0 = blockIdx.y * 128, n0 = blockIdx.x * 128;
    const int lrow = lane & 15;
    const int lcolb = (lane >> 4) * 16;
    const int row = tid >> 2, seg = tid & 3;   // loader: 128 rows x 4 segs of 32B

    float acc[2][4][4] = {};

    auto ldchunk = [&](int c, int s) {
        const int k0 = c << 6;
        const uint32_t st = sb + s * GST;
        const uint32_t so = row * GRS + seg * 32;
        const __nv_bfloat16* ga = Ahi + (size_t)(m0 + row) * K + k0 + seg * 16;
        const __nv_bfloat16* gb = Alo + (size_t)(m0 + row) * K + k0 + seg * 16;
        const __nv_bfloat16* gc = Bhi + (size_t)(n0 + row) * K + k0 + seg * 16;
        const __nv_bfloat16* gd = Blo + (size_t)(n0 + row) * K + k0 + seg * 16;
        cpa16(st + G_AH + so, ga);       cpa16(st + G_AH + so + 16, ga + 8);
        cpa16(st + G_AL + so, gb);       cpa16(st + G_AL + so + 16, gb + 8);
        cpa16(st + G_BH + so, gc);       cpa16(st + G_BH + so + 16, gc + 8);
        cpa16(st + G_BL + so, gd);       cpa16(st + G_BL + so + 16, gd + 8);
    };

    const int nch = K >> 6;
    ldchunk(0, 0);
    CP_COMMIT();
    if (nch > 1) { ldchunk(1, 1); CP_COMMIT(); }

    for (int c = 0; c < nch; c++) {
        if (c + 2 < nch) {
            ldchunk(c + 2, (c + 2) % 3);
            CP_COMMIT();
            CP_WAIT2();
        } else if (c + 1 < nch) {
            CP_WAIT1();
        } else {
            CP_WAIT0();
        }
        __syncthreads();
        const uint32_t st = sb + (c % 3) * GST;
#pragma unroll
        for (int kt = 0; kt < 4; kt++) {
            uint32_t aH[2][4], aL[2][4];
#pragma unroll
            for (int mf = 0; mf < 2; mf++) {
                const uint32_t ar = (wm * 32 + mf * 16 + lrow) * GRS + kt * 32 + lcolb;
                ldmx4(aH[mf], st + G_AH + ar);
                ldmx4(aL[mf], st + G_AL + ar);
            }
#pragma unroll
            for (int nfp = 0; nfp < 2; nfp++) {
                uint32_t r[4], s[4];
                const uint32_t br = (wn * 32 + nfp * 16 + lrow) * GRS + kt * 32 + lcolb;
                ldmx4(r, st + G_BH + br);
                ldmx4(s, st + G_BL + br);
#pragma unroll
                for (int mf = 0; mf < 2; mf++) {
                    mma_bf16(acc[mf][2 * nfp], aH[mf], r[0], r[2]);
                    mma_bf16(acc[mf][2 * nfp + 1], aH[mf], r[1], r[3]);
                    mma_bf16(acc[mf][2 * nfp], aH[mf], s[0], s[2]);
                    mma_bf16(acc[mf][2 * nfp + 1], aH[mf], s[1], s[3]);
                    mma_bf16(acc[mf][2 * nfp], aL[mf], r[0], r[2]);
                    mma_bf16(acc[mf][2 * nfp + 1], aL[mf], r[1], r[3]);
                }
            }
        }
        __syncthreads();
    }

    // epilogue
    const int g = lane >> 2, tq = lane & 3;
#pragma unroll
    for (int mf = 0; mf < 2; mf++) {
        const int r0 = m0 + wm * 32 + mf * 16 + g;
        const int r1 = r0 + 8;
#pragma unroll
        for (int nf = 0; nf < 4; nf++) {
            const int col = n0 + wn * 32 + nf * 8 + 2 * tq;
            const float b0 = bias[col], b1 = bias[col + 1];
            float v0 = acc[mf][nf][0] + b0, v1 = acc[mf][nf][1] + b1;
            float v2 = acc[mf][nf][2] + b0, v3 = acc[mf][nf][3] + b1;
            if (mode == 0) {
                *(float2*)(f32A + (size_t)r0 * N + col) = {v0, v1};
                *(float2*)(f32A + (size_t)r1 * N + col) = {v2, v3};
            } else if (mode == 1) {
                *(uint32_t*)(hA + (size_t)r0 * N + col) =
                    packh2(v0 * SCALE_LOG2E, v1 * SCALE_LOG2E);
                *(uint32_t*)(hA + (size_t)r1 * N + col) =
                    packh2(v2 * SCALE_LOG2E, v3 * SCALE_LOG2E);
            } else {
                const int d0 = (r0 < MR) ? r0 : r0 + L_LEN;
                const int d1 = (r1 < MR) ? r1 : r1 + L_LEN;
                if (col < D) {  // key half: fp32 out + fp16 single for attn
                    *(float2*)(f32A + (size_t)d0 * D + col) = {v0, v1};
                    *(float2*)(f32A + (size_t)d1 * D + col) = {v2, v3};
                    *(uint32_t*)(hA + (size_t)d0 * D + col) = packh2(v0, v1);
                    *(uint32_t*)(hA + (size_t)d1 * D + col) = packh2(v2, v3);
                } else {        // value half: fp32 out + bf16 hi/lo
                    const int cc = col - D;
                    *(float2*)(f32B + (size_t)d0 * D + cc) = {v0, v1};
                    *(float2*)(f32B + (size_t)d1 * D + cc) = {v2, v3};
                    uint32_t h01, l01;
                    fsplit2(v0, v1, h01, l01);
                    *(uint32_t*)(bhB + (size_t)d0 * D + cc) = h01;
                    *(uint32_t*)(blB + (size_t)d0 * D + cc) = l01;
                    fsplit2(v2, v3, h01, l01);
                    *(uint32_t*)(bhB + (size_t)d1 * D + cc) = h01;
                    *(uint32_t*)(blB + (size_t)d1 * D + cc) = l01;
                }
            }
        }
    }
}

// ---------------- mma.sync flash attention (fp16 S, bf16 3-term PV) ----------
// grid (QLEN/128, NH). 16 warps = 8 q-groups x 2 kv-halves. KV chunks of 128.
// Q/K single fp16 (S err ~2e-4 abs, fine); V bf16 hi/lo (PV 3-term).
#define A_K  0
#define A_VH 18432
#define A_VL 36864
#define AST  55296                 // stage: K + VH + VL
#define A_Q  (2 * AST)
#define ATT_SMEM (2 * AST + 18432)

__global__ void __launch_bounds__(512, 1) attn_mma(
    const __half* __restrict__ qf, const __half* __restrict__ kf,
    const __nv_bfloat16* __restrict__ vhi, const __nv_bfloat16* __restrict__ vlo,
    __nv_bfloat16* __restrict__ ahi, __nv_bfloat16* __restrict__ alo) {
    extern __shared__ char sm[];
    const uint32_t sb = s2u(sm);
    const int tid = threadIdx.x;
    const int lane = tid & 31, wid = tid >> 5;
    const int qw = wid >> 1, kw = wid & 1;   // q-group 0..7, kv-half 0..1
    const int h = blockIdx.y;
    const int q0 = blockIdx.x * 128;
    const int lrow = lane & 15;
    const int lcolb = (lane >> 4) * 16;
    const int row = tid >> 2, seg = tid & 3;

    // Q tile via cp.async (group 0): fp16 single, 128 rows x 128B
    {
        const uint32_t so = row * GRS + seg * 32;
        const __half* pq = qf + (size_t)(q0 + row) * D + h * HD + seg * 16;
        cpa16(sb + A_Q + so, pq);       cpa16(sb + A_Q + so + 16, pq + 8);
    }
    CP_COMMIT();

    auto ldchunk = [&](int kv0, int s) {
        const uint32_t st = sb + s * AST;
        const uint32_t so = row * GRS + seg * 32;
        const __half* pk = kf + (size_t)(kv0 + row) * D + h * HD + seg * 16;
        const __nv_bfloat16* pvh = vhi + (size_t)(kv0 + row) * D + h * HD + seg * 16;
        const __nv_bfloat16* pvl = vlo + (size_t)(kv0 + row) * D + h * HD + seg * 16;
        cpa16(st + A_K + so, pk);       cpa16(st + A_K + so + 16, pk + 8);
        cpa16(st + A_VH + so, pvh);     cpa16(st + A_VH + so + 16, pvh + 8);
        cpa16(st + A_VL + so, pvl);     cpa16(st + A_VL + so + 16, pvl + 8);
    };

    ldchunk(0, 0);
    CP_COMMIT();

    CP_WAIT1();          // Q resident; chunk 0 may still be in flight
    __syncthreads();

    float oacc[8][4] = {};       // partial O for this warp's kv half
    float lsum0 = 0.f, lsum1 = 0.f;

    const int NCH = KVLEN / 128;  // 30
    for (int c = 0; c < NCH; c++) {
        if (c + 1 < NCH) {
            ldchunk((c + 1) * 128, (c + 1) & 1);
            CP_COMMIT();
            CP_WAIT1();
        } else {
            CP_WAIT0();
        }
        __syncthreads();
        const uint32_t st = sb + (c & 1) * AST;

        float sacc[8][4] = {};
        // S = q . k^T for this warp's 64-kv half (single-term fp16)
#pragma unroll
        for (int kt = 0; kt < 4; kt++) {
            uint32_t qF[4];
            const uint32_t ar = (qw * 16 + lrow) * GRS + kt * 32 + lcolb;
            ldmx4(qF, sb + A_Q + ar);
#pragma unroll
            for (int nfp = 0; nfp < 4; nfp++) {
                uint32_t r[4];
                const uint32_t br =
                    (kw * 64 + nfp * 16 + lrow) * GRS + kt * 32 + lcolb;
                ldmx4(r, st + A_K + br);
                mma_f16(sacc[2 * nfp], qF, r[0], r[2]);
                mma_f16(sacc[2 * nfp + 1], qF, r[1], r[3]);
            }
        }
        // p = exp2(S') -> P fragments (hi/lo) -> partial O += P . V (3-term)
#pragma unroll
        for (int kt2 = 0; kt2 < 4; kt2++) {
            const float* s0 = sacc[2 * kt2];
            const float* s1 = sacc[2 * kt2 + 1];
            float p0 = exp2f(s0[0]), p1 = exp2f(s0[1]);
            float p2 = exp2f(s0[2]), p3 = exp2f(s0[3]);
            float p4 = exp2f(s1[0]), p5 = exp2f(s1[1]);
            float p6 = exp2f(s1[2]), p7 = exp2f(s1[3]);
            lsum0 += p0 + p1 + p4 + p5;
            lsum1 += p2 + p3 + p6 + p7;
            uint32_t aPH[4], aPL[4];
            fsplit2(p0, p1, aPH[0], aPL[0]);
            fsplit2(p2, p3, aPH[1], aPL[1]);
            fsplit2(p4, p5, aPH[2], aPL[2]);
            fsplit2(p6, p7, aPH[3], aPL[3]);
            // V rows for this slice: kw*64 + kt2*16
            const int vr0 = (kw * 4 + kt2) * 16 + ((lane >> 4) << 3) + (lane & 7);
            const uint32_t vcb = ((lane & 8) << 1);
#pragma unroll
            for (int df = 0; df < 4; df++) {
                uint32_t r[4], s[4];
                const uint32_t br = vr0 * GRS + df * 32 + vcb;
                ldmx4t(r, st + A_VH + br);
                ldmx4t(s, st + A_VL + br);
                mma_bf16(oacc[2 * df], aPH, r[0], r[2]);
                mma_bf16(oacc[2 * df + 1], aPH, r[1], r[3]);
                mma_bf16(oacc[2 * df], aPH, s[0], s[2]);
                mma_bf16(oacc[2 * df + 1], aPH, s[1], s[3]);
                mma_bf16(oacc[2 * df], aPL, r[0], r[2]);
                mma_bf16(oacc[2 * df + 1], aPL, r[1], r[3]);
            }
        }
        __syncthreads();
    }

    // reduce the two kv-half partials through smem (stage area is free now)
    float* red = (float*)sm;
    if (kw == 1) {
        float* dst = red + (qw * 32 + lane) * 34;
#pragma unroll
        for (int df = 0; df < 8; df++)
#pragma unroll
            for (int j = 0; j < 4; j++) dst[df * 4 + j] = oacc[df][j];
        dst[32] = lsum0;
        dst[33] = lsum1;
    }
    __syncthreads();
    if (kw == 0) {
        const float* src = red + (qw * 32 + lane) * 34;
#pragma unroll
        for (int df = 0; df < 8; df++)
#pragma unroll
            for (int j = 0; j < 4; j++) oacc[df][j] += src[df * 4 + j];
        lsum0 += src[32];
        lsum1 += src[33];

        // reduce row sums across the 4 lanes of each quad
#pragma unroll
        for (int off = 1; off <= 2; off <<= 1) {
            lsum0 += __shfl_xor_sync(0xffffffffu, lsum0, off);
            lsum1 += __shfl_xor_sync(0xffffffffu, lsum1, off);
        }
        const float inv0 = 1.0f / lsum0, inv1 = 1.0f / lsum1;

        const int g = lane >> 2, tq = lane & 3;
        const int r0 = q0 + qw * 16 + g, r1 = r0 + 8;
#pragma unroll
        for (int df = 0; df < 8; df++) {
            const int col = df * 8 + 2 * tq;
            uint32_t h01, l01;
            fsplit2(oacc[df][0] * inv0, oacc[df][1] * inv0, h01, l01);
            *(uint32_t*)(ahi + (size_t)r0 * D + h * HD + col) = h01;
            *(uint32_t*)(alo + (size_t)r0 * D + h * HD + col) = l01;
            fsplit2(oacc[df][2] * inv1, oacc[df][3] * inv1, h01, l01);
            *(uint32_t*)(ahi + (size_t)r1 * D + h * HD + col) = h01;
            *(uint32_t*)(alo + (size_t)r1 * D + h * HD + col) = l01;
        }
    }
}

// ---------------------------------------------------------------------------
extern "C" void kernel_launch(void* const* d_in, const int* in_sizes, int n_in,
                              void* d_out, int out_size) {
    const float* ut  = (const float*)d_in[0];
    const float* rc  = (const float*)d_in[1];
    const float* mem = (const float*)d_in[2];
    const float* lck = (const float*)d_in[3];
    const float* lcv = (const float*)d_in[4];
    const float* Wq  = (const float*)d_in[5];
    const float* bq  = (const float*)d_in[6];
    const float* Wkv = (const float*)d_in[7];
    const float* bkv = (const float*)d_in[8];
    const float* Wo  = (const float*)d_in[9];
    const float* bo  = (const float*)d_in[10];

    float* out  = (float*)d_out;
    float* keyb = out + KEY_OFF;
    float* valb = out + VAL_OFF;

    __nv_bfloat16 *qih, *qil, *kvh, *kvl, *wqh, *wql, *wkh, *wkl, *woh, *wol;
    __nv_bfloat16 *vh, *vl, *ath, *atl;
    __half *qf, *kf;
    cudaGetSymbolAddress((void**)&qih, g_qin_hi);  cudaGetSymbolAddress((void**)&qil, g_qin_lo);
    cudaGetSymbolAddress((void**)&kvh, g_kvin_hi); cudaGetSymbolAddress((void**)&kvl, g_kvin_lo);
    cudaGetSymbolAddress((void**)&wqh, g_wq_hi);   cudaGetSymbolAddress((void**)&wql, g_wq_lo);
    cudaGetSymbolAddress((void**)&wkh, g_wkv_hi);  cudaGetSymbolAddress((void**)&wkl, g_wkv_lo);
    cudaGetSymbolAddress((void**)&woh, g_wo_hi);   cudaGetSymbolAddress((void**)&wol, g_wo_lo);
    cudaGetSymbolAddress((void**)&qf, g_q_f16);    cudaGetSymbolAddress((void**)&kf, g_k_f16);
    cudaGetSymbolAddress((void**)&vh, g_v_hi);     cudaGetSymbolAddress((void**)&vl, g_v_lo);
    cudaGetSymbolAddress((void**)&ath, g_at_hi);   cudaGetSymbolAddress((void**)&atl, g_at_lo);

    cudaFuncSetAttribute(gemm_mma, cudaFuncAttributeMaxDynamicSharedMemorySize, GEMM_SMEM);
    cudaFuncSetAttribute(attn_mma, cudaFuncAttributeMaxDynamicSharedMemorySize, ATT_SMEM);

    // launch 0: weights
    conv_w<<<dim3(2048, 3), 256>>>(Wq, Wkv, Wo, wqh, wql, wkh, wkl, woh, wol);
    // launch 1: activations
    conv_act<<<dim3(2048, 5), 256>>>(rc, ut, mem, qih, qil, kvh, kvl);
    // launch 2: left-context
    conv_lc<<<(L_LEN * D) / 256, 256>>>(lck, lcv, keyb, valb, kf, vh, vl);

    // launch 3: q = (q_in @ Wq^T + bq) * 0.125*log2e -> fp16
    gemm_mma<<<dim3(D / 128, QLEN / 128), 512, GEMM_SMEM>>>(
        qih, qil, wqh, wql, bq, D, D, 1,
        nullptr, nullptr, qf, nullptr, nullptr);
    // launch 4: kv = kv_in @ Wkv^T + bkv -> key/value fp32 (+L-shift) + k fp16 + v hi/lo
    gemm_mma<<<dim3(2 * D / 128, KVIN / 128), 512, GEMM_SMEM>>>(
        kvh, kvl, wkh, wkl, bkv, D, 2 * D, 2,
        keyb, valb, kf, vh, vl);
    // launch 5 (ncu -s 5 target): attention -> attn hi/lo
    attn_mma<<<dim3(QLEN / 128, NH), 512, ATT_SMEM>>>(
        qf, kf, vh, vl, ath, atl);
    // launch 6: out = attn @ Wo^T + bo
    gemm_mma<<<dim3(D / 128, QLEN / 128), 512, GEMM_SMEM>>>(
        ath, atl, woh, wol, bo, D, D, 0,
        out, nullptr, nullptr, nullptr, nullptr);
}

// round 16
// speedup vs baseline: 1.8015x; 1.2299x over previous
#include <cuda_runtime.h>
#include <cuda_bf16.h>
#include <cuda_fp16.h>
#include <cstdint>

#define D 1024
#define NH 16
#define HD 64
#define U_LEN 2048
#define R_LEN 256
#define L_LEN 1024
#define M_LEN 512
#define QLEN 2304   // U + R
#define KVLEN 3840  // M + R + L + U
#define KVIN 2816   // M + R + U
#define MR 768      // M + R

#define KEY_OFF (QLEN * D)
#define VAL_OFF (KEY_OFF + KVLEN * D)

#define SCALE_LOG2E 0.1803368801111204f   // 0.125 * log2(e)

// ---------------- scratch (allocation-free rule: __device__ globals) --------
__device__ __nv_bfloat16 g_qin_hi[QLEN * D], g_qin_lo[QLEN * D];
__device__ __nv_bfloat16 g_kvin_hi[KVIN * D], g_kvin_lo[KVIN * D];
__device__ __nv_bfloat16 g_wq_hi[D * D], g_wq_lo[D * D];
__device__ __nv_bfloat16 g_wkv_hi[2 * D * D], g_wkv_lo[2 * D * D];
__device__ __nv_bfloat16 g_wo_hi[D * D], g_wo_lo[D * D];
__device__ __half       g_q_f16[QLEN * D];    // q * 0.125*log2e, fp16 single
__device__ __half       g_k_f16[KVLEN * D];   // key, fp16 single (attn use)
__device__ __half       g_v_f16[KVLEN * D];   // value, fp16 single (attn use)
__device__ __nv_bfloat16 g_at_hi[QLEN * D], g_at_lo[QLEN * D];

// ---------------- helpers ---------------------------------------------------
static __device__ __forceinline__ uint32_t s2u(const void* p) {
    uint32_t a;
    asm("{ .reg .u64 t; cvta.to.shared.u64 t, %1; cvt.u32.u64 %0, t; }"
        : "=r"(a) : "l"(p));
    return a;
}

static __device__ __forceinline__ void ldmx4(uint32_t* r, uint32_t addr) {
    asm volatile("ldmatrix.sync.aligned.m8n8.x4.shared.b16 {%0,%1,%2,%3}, [%4];"
                 : "=r"(r[0]), "=r"(r[1]), "=r"(r[2]), "=r"(r[3]) : "r"(addr));
}
static __device__ __forceinline__ void ldmx4t(uint32_t* r, uint32_t addr) {
    asm volatile("ldmatrix.sync.aligned.m8n8.x4.trans.shared.b16 {%0,%1,%2,%3}, [%4];"
                 : "=r"(r[0]), "=r"(r[1]), "=r"(r[2]), "=r"(r[3]) : "r"(addr));
}

static __device__ __forceinline__ void mma_bf16(float* c, const uint32_t* a,
                                                uint32_t b0, uint32_t b1) {
    asm volatile("mma.sync.aligned.m16n8k16.row.col.f32.bf16.bf16.f32 "
                 "{%0,%1,%2,%3}, {%4,%5,%6,%7}, {%8,%9}, {%0,%1,%2,%3};"
                 : "+f"(c[0]), "+f"(c[1]), "+f"(c[2]), "+f"(c[3])
                 : "r"(a[0]), "r"(a[1]), "r"(a[2]), "r"(a[3]), "r"(b0), "r"(b1));
}
static __device__ __forceinline__ void mma_f16(float* c, const uint32_t* a,
                                               uint32_t b0, uint32_t b1) {
    asm volatile("mma.sync.aligned.m16n8k16.row.col.f32.f16.f16.f32 "
                 "{%0,%1,%2,%3}, {%4,%5,%6,%7}, {%8,%9}, {%0,%1,%2,%3};"
                 : "+f"(c[0]), "+f"(c[1]), "+f"(c[2]), "+f"(c[3])
                 : "r"(a[0]), "r"(a[1]), "r"(a[2]), "r"(a[3]), "r"(b0), "r"(b1));
}

static __device__ __forceinline__ void cpa16(uint32_t s, const void* g) {
    asm volatile("cp.async.cg.shared.global [%0], [%1], 16;" :: "r"(s), "l"(g));
}
#define CP_COMMIT() asm volatile("cp.async.commit_group;" ::: "memory")
#define CP_WAIT2() asm volatile("cp.async.wait_group 2;" ::: "memory")
#define CP_WAIT1() asm volatile("cp.async.wait_group 1;" ::: "memory")
#define CP_WAIT0() asm volatile("cp.async.wait_group 0;" ::: "memory")

// Fast pair split: hi = truncate-to-bf16 (one PRMT for the pair), lo = exact
// residual rounded to bf16x2 (one cvt). Dropped lo*lo term <= 2^-16 relative.
static __device__ __forceinline__ void fsplit2(float x0, float x1,
                                               uint32_t& hi01, uint32_t& lo01) {
    const uint32_t u0 = __float_as_uint(x0), u1 = __float_as_uint(x1);
    hi01 = __byte_perm(u0, u1, 0x7632);   // [hi16(x0) | hi16(x1)<<16]
    const float l0 = x0 - __uint_as_float(u0 & 0xFFFF0000u);
    const float l1 = x1 - __uint_as_float(u1 & 0xFFFF0000u);
    asm("cvt.rn.bf16x2.f32 %0, %1, %2;" : "=r"(lo01) : "f"(l1), "f"(l0));
}
static __device__ __forceinline__ uint32_t packh2(float a, float b) {
    __half2 h = __floats2half2_rn(a, b);
    return *(uint32_t*)&h;
}

// ---------------- batched conversion kernels ---------------------------------
static __device__ __forceinline__ void conv_seg(const float* __restrict__ s,
                                                __nv_bfloat16* __restrict__ hi,
                                                __nv_bfloat16* __restrict__ lo,
                                                int n4, int i) {
    if (i >= n4) return;
    float4 v = ((const float4*)s)[i];
    uint32_t h01, l01, h23, l23;
    fsplit2(v.x, v.y, h01, l01);
    fsplit2(v.z, v.w, h23, l23);
    ((uint32_t*)hi)[2 * i] = h01;
    ((uint32_t*)hi)[2 * i + 1] = h23;
    ((uint32_t*)lo)[2 * i] = l01;
    ((uint32_t*)lo)[2 * i + 1] = l23;
}

__global__ void conv_w(const float* __restrict__ Wq, const float* __restrict__ Wkv,
                       const float* __restrict__ Wo,
                       __nv_bfloat16* wqh, __nv_bfloat16* wql,
                       __nv_bfloat16* wkh, __nv_bfloat16* wkl,
                       __nv_bfloat16* woh, __nv_bfloat16* wol) {
    const int i = blockIdx.x * blockDim.x + threadIdx.x;
    switch (blockIdx.y) {
        case 0: conv_seg(Wq, wqh, wql, D * D / 4, i); break;
        case 1: conv_seg(Wkv, wkh, wkl, 2 * D * D / 4, i); break;
        default: conv_seg(Wo, woh, wol, D * D / 4, i); break;
    }
}

__global__ void conv_act(const float* __restrict__ rc, const float* __restrict__ ut,
                         const float* __restrict__ mem,
                         __nv_bfloat16* qih, __nv_bfloat16* qil,
                         __nv_bfloat16* kvh, __nv_bfloat16* kvl) {
    const int i = blockIdx.x * blockDim.x + threadIdx.x;
    switch (blockIdx.y) {
        case 0: conv_seg(rc, qih, qil, R_LEN * D / 4, i); break;
        case 1: conv_seg(ut, qih + (size_t)R_LEN * D, qil + (size_t)R_LEN * D,
                         U_LEN * D / 4, i); break;
        case 2: conv_seg(mem, kvh, kvl, M_LEN * D / 4, i); break;
        case 3: conv_seg(rc, kvh + (size_t)M_LEN * D, kvl + (size_t)M_LEN * D,
                         R_LEN * D / 4, i); break;
        default: conv_seg(ut, kvh + (size_t)MR * D, kvl + (size_t)MR * D,
                          U_LEN * D / 4, i); break;
    }
}

__global__ void conv_lc(const float* __restrict__ lck, const float* __restrict__ lcv,
                        float* __restrict__ keyb, float* __restrict__ valb,
                        __half* __restrict__ kf16, __half* __restrict__ vf16) {
    int i = blockIdx.x * blockDim.x + threadIdx.x;  // 0 .. L*D-1
    int r = i >> 10, c = i & 1023;
    float kv = lck[i], vv = lcv[i];
    size_t o = (size_t)(MR + r) * D + c;
    keyb[o] = kv;
    valb[o] = vv;
    kf16[o] = __float2half(kv);
    vf16[o] = __float2half(vv);
}

// ---------------- split-bf16 mma.sync GEMM (512 thr, 3-stage cp.async) -------
// C[M,N] = (Ahi+Alo)[M,K] @ (Bhi+Blo)[N,K]^T + bias (3-term split).
// Block tile 128x128, 16 warps 4x4 (warp tile 32x32); K-chunks of 64.
// mode 0: fp32 out. mode 1: (acc+bias)*scale -> hA fp16 (q path).
// mode 2: KV: key half -> f32A(keyb) + hA fp16 with L-shift; value half ->
//         f32B(valb) + hB fp16.
#define GRS 144
#define GST 73728                 // stage size: 4 tensors * 128 * 144
#define G_AH 0
#define G_AL 18432
#define G_BH 36864
#define G_BL 55296
#define GEMM_SMEM (3 * GST)

__global__ void __launch_bounds__(512, 1) gemm_mma(
    const __nv_bfloat16* __restrict__ Ahi, const __nv_bfloat16* __restrict__ Alo,
    const __nv_bfloat16* __restrict__ Bhi, const __nv_bfloat16* __restrict__ Blo,
    const float* __restrict__ bias, int K, int N, int mode,
    float* __restrict__ f32A, float* __restrict__ f32B,
    __half* __restrict__ hA, __half* __restrict__ hB) {
    extern __shared__ char sm[];
    const uint32_t sb = s2u(sm);
    const int tid = threadIdx.x;
    const int lane = tid & 31, wid = tid >> 5;
    const int wm = wid >> 2, wn = wid & 3;
    const int m0 = blockIdx.y * 128, n0 = blockIdx.x * 128;
    const int lrow = lane & 15;
    const int lcolb = (lane >> 4) * 16;
    const int row = tid >> 2, seg = tid & 3;   // loader: 128 rows x 4 segs of 32B

    float acc[2][4][4] = {};

    auto ldchunk = [&](int c, int s) {
        const int k0 = c << 6;
        const uint32_t st = sb + s * GST;
        const uint32_t so = row * GRS + seg * 32;
        const __nv_bfloat16* ga = Ahi + (size_t)(m0 + row) * K + k0 + seg * 16;
        const __nv_bfloat16* gb = Alo + (size_t)(m0 + row) * K + k0 + seg * 16;
        const __nv_bfloat16* gc = Bhi + (size_t)(n0 + row) * K + k0 + seg * 16;
        const __nv_bfloat16* gd = Blo + (size_t)(n0 + row) * K + k0 + seg * 16;
        cpa16(st + G_AH + so, ga);       cpa16(st + G_AH + so + 16, ga + 8);
        cpa16(st + G_AL + so, gb);       cpa16(st + G_AL + so + 16, gb + 8);
        cpa16(st + G_BH + so, gc);       cpa16(st + G_BH + so + 16, gc + 8);
        cpa16(st + G_BL + so, gd);       cpa16(st + G_BL + so + 16, gd + 8);
    };

    const int nch = K >> 6;
    ldchunk(0, 0);
    CP_COMMIT();
    if (nch > 1) { ldchunk(1, 1); CP_COMMIT(); }

    for (int c = 0; c < nch; c++) {
        if (c + 2 < nch) {
            ldchunk(c + 2, (c + 2) % 3);
            CP_COMMIT();
            CP_WAIT2();
        } else if (c + 1 < nch) {
            CP_WAIT1();
        } else {
            CP_WAIT0();
        }
        __syncthreads();
        const uint32_t st = sb + (c % 3) * GST;
#pragma unroll
        for (int kt = 0; kt < 4; kt++) {
            uint32_t aH[2][4], aL[2][4];
#pragma unroll
            for (int mf = 0; mf < 2; mf++) {
                const uint32_t ar = (wm * 32 + mf * 16 + lrow) * GRS + kt * 32 + lcolb;
                ldmx4(aH[mf], st + G_AH + ar);
                ldmx4(aL[mf], st + G_AL + ar);
            }
#pragma unroll
            for (int nfp = 0; nfp < 2; nfp++) {
                uint32_t r[4], s[4];
                const uint32_t br = (wn * 32 + nfp * 16 + lrow) * GRS + kt * 32 + lcolb;
                ldmx4(r, st + G_BH + br);
                ldmx4(s, st + G_BL + br);
#pragma unroll
                for (int mf = 0; mf < 2; mf++) {
                    mma_bf16(acc[mf][2 * nfp], aH[mf], r[0], r[2]);
                    mma_bf16(acc[mf][2 * nfp + 1], aH[mf], r[1], r[3]);
                    mma_bf16(acc[mf][2 * nfp], aH[mf], s[0], s[2]);
                    mma_bf16(acc[mf][2 * nfp + 1], aH[mf], s[1], s[3]);
                    mma_bf16(acc[mf][2 * nfp], aL[mf], r[0], r[2]);
                    mma_bf16(acc[mf][2 * nfp + 1], aL[mf], r[1], r[3]);
                }
            }
        }
        __syncthreads();
    }

    // epilogue
    const int g = lane >> 2, tq = lane & 3;
#pragma unroll
    for (int mf = 0; mf < 2; mf++) {
        const int r0 = m0 + wm * 32 + mf * 16 + g;
        const int r1 = r0 + 8;
#pragma unroll
        for (int nf = 0; nf < 4; nf++) {
            const int col = n0 + wn * 32 + nf * 8 + 2 * tq;
            const float b0 = bias[col], b1 = bias[col + 1];
            float v0 = acc[mf][nf][0] + b0, v1 = acc[mf][nf][1] + b1;
            float v2 = acc[mf][nf][2] + b0, v3 = acc[mf][nf][3] + b1;
            if (mode == 0) {
                *(float2*)(f32A + (size_t)r0 * N + col) = {v0, v1};
                *(float2*)(f32A + (size_t)r1 * N + col) = {v2, v3};
            } else if (mode == 1) {
                *(uint32_t*)(hA + (size_t)r0 * N + col) =
                    packh2(v0 * SCALE_LOG2E, v1 * SCALE_LOG2E);
                *(uint32_t*)(hA + (size_t)r1 * N + col) =
                    packh2(v2 * SCALE_LOG2E, v3 * SCALE_LOG2E);
            } else {
                const int d0 = (r0 < MR) ? r0 : r0 + L_LEN;
                const int d1 = (r1 < MR) ? r1 : r1 + L_LEN;
                if (col < D) {  // key half: fp32 out + fp16 single for attn
                    *(float2*)(f32A + (size_t)d0 * D + col) = {v0, v1};
                    *(float2*)(f32A + (size_t)d1 * D + col) = {v2, v3};
                    *(uint32_t*)(hA + (size_t)d0 * D + col) = packh2(v0, v1);
                    *(uint32_t*)(hA + (size_t)d1 * D + col) = packh2(v2, v3);
                } else {        // value half: fp32 out + fp16 single for attn
                    const int cc = col - D;
                    *(float2*)(f32B + (size_t)d0 * D + cc) = {v0, v1};
                    *(float2*)(f32B + (size_t)d1 * D + cc) = {v2, v3};
                    *(uint32_t*)(hB + (size_t)d0 * D + cc) = packh2(v0, v1);
                    *(uint32_t*)(hB + (size_t)d1 * D + cc) = packh2(v2, v3);
                }
            }
        }
    }
}

// ---------------- mma.sync flash attention (all-fp16 S and PV) --------------
// grid (QLEN/128, NH). 16 warps = 8 q-groups x 2 kv-halves. KV chunks of 128.
// Q/K/V single fp16; P fp16. O fp32 partials accumulate across chunks;
// one smem reduction at the end. Output attn as bf16 hi/lo (exact 2-term).
#define A_K  0
#define A_V  18432
#define AST  36864                 // stage: K + V
#define A_Q  (2 * AST)
#define ATT_SMEM (2 * AST + 18432)

__global__ void __launch_bounds__(512, 1) attn_mma(
    const __half* __restrict__ qf, const __half* __restrict__ kf,
    const __half* __restrict__ vf,
    __nv_bfloat16* __restrict__ ahi, __nv_bfloat16* __restrict__ alo) {
    extern __shared__ char sm[];
    const uint32_t sb = s2u(sm);
    const int tid = threadIdx.x;
    const int lane = tid & 31, wid = tid >> 5;
    const int qw = wid >> 1, kw = wid & 1;   // q-group 0..7, kv-half 0..1
    const int h = blockIdx.y;
    const int q0 = blockIdx.x * 128;
    const int lrow = lane & 15;
    const int lcolb = (lane >> 4) * 16;
    const int row = tid >> 2, seg = tid & 3;

    // Q tile via cp.async (group 0): fp16 single, 128 rows x 128B
    {
        const uint32_t so = row * GRS + seg * 32;
        const __half* pq = qf + (size_t)(q0 + row) * D + h * HD + seg * 16;
        cpa16(sb + A_Q + so, pq);       cpa16(sb + A_Q + so + 16, pq + 8);
    }
    CP_COMMIT();

    auto ldchunk = [&](int kv0, int s) {
        const uint32_t st = sb + s * AST;
        const uint32_t so = row * GRS + seg * 32;
        const __half* pk = kf + (size_t)(kv0 + row) * D + h * HD + seg * 16;
        const __half* pv = vf + (size_t)(kv0 + row) * D + h * HD + seg * 16;
        cpa16(st + A_K + so, pk);       cpa16(st + A_K + so + 16, pk + 8);
        cpa16(st + A_V + so, pv);       cpa16(st + A_V + so + 16, pv + 8);
    };

    ldchunk(0, 0);
    CP_COMMIT();

    CP_WAIT1();          // Q resident; chunk 0 may still be in flight
    __syncthreads();

    float oacc[8][4] = {};       // partial O for this warp's kv half
    float lsum0 = 0.f, lsum1 = 0.f;

    const int NCH = KVLEN / 128;  // 30
    for (int c = 0; c < NCH; c++) {
        if (c + 1 < NCH) {
            ldchunk((c + 1) * 128, (c + 1) & 1);
            CP_COMMIT();
            CP_WAIT1();
        } else {
            CP_WAIT0();
        }
        __syncthreads();
        const uint32_t st = sb + (c & 1) * AST;

        float sacc[8][4] = {};
        // S = q . k^T for this warp's 64-kv half (single-term fp16)
#pragma unroll
        for (int kt = 0; kt < 4; kt++) {
            uint32_t qF[4];
            const uint32_t ar = (qw * 16 + lrow) * GRS + kt * 32 + lcolb;
            ldmx4(qF, sb + A_Q + ar);
#pragma unroll
            for (int nfp = 0; nfp < 4; nfp++) {
                uint32_t r[4];
                const uint32_t br =
                    (kw * 64 + nfp * 16 + lrow) * GRS + kt * 32 + lcolb;
                ldmx4(r, st + A_K + br);
                mma_f16(sacc[2 * nfp], qF, r[0], r[2]);
                mma_f16(sacc[2 * nfp + 1], qF, r[1], r[3]);
            }
        }
        // p = exp2(S') -> P fp16 fragments -> partial O += P . V (fp16 single)
#pragma unroll
        for (int kt2 = 0; kt2 < 4; kt2++) {
            const float* s0 = sacc[2 * kt2];
            const float* s1 = sacc[2 * kt2 + 1];
            float p0 = exp2f(s0[0]), p1 = exp2f(s0[1]);
            float p2 = exp2f(s0[2]), p3 = exp2f(s0[3]);
            float p4 = exp2f(s1[0]), p5 = exp2f(s1[1]);
            float p6 = exp2f(s1[2]), p7 = exp2f(s1[3]);
            lsum0 += p0 + p1 + p4 + p5;
            lsum1 += p2 + p3 + p6 + p7;
            uint32_t aP[4];
            aP[0] = packh2(p0, p1);
            aP[1] = packh2(p2, p3);
            aP[2] = packh2(p4, p5);
            aP[3] = packh2(p6, p7);
            // V rows for this slice: kw*64 + kt2*16
            const int vr0 = (kw * 4 + kt2) * 16 + ((lane >> 4) << 3) + (lane & 7);
            const uint32_t vcb = ((lane & 8) << 1);
#pragma unroll
            for (int df = 0; df < 4; df++) {
                uint32_t r[4];
                const uint32_t br = vr0 * GRS + df * 32 + vcb;
                ldmx4t(r, st + A_V + br);
                mma_f16(oacc[2 * df], aP, r[0], r[2]);
                mma_f16(oacc[2 * df + 1], aP, r[1], r[3]);
            }
        }
        __syncthreads();
    }

    // reduce the two kv-half partials through smem (stage area is free now)
    float* red = (float*)sm;
    if (kw == 1) {
        float* dst = red + (qw * 32 + lane) * 34;
#pragma unroll
        for (int df = 0; df < 8; df++)
#pragma unroll
            for (int j = 0; j < 4; j++) dst[df * 4 + j] = oacc[df][j];
        dst[32] = lsum0;
        dst[33] = lsum1;
    }
    __syncthreads();
    if (kw == 0) {
        const float* src = red + (qw * 32 + lane) * 34;
#pragma unroll
        for (int df = 0; df < 8; df++)
#pragma unroll
            for (int j = 0; j < 4; j++) oacc[df][j] += src[df * 4 + j];
        lsum0 += src[32];
        lsum1 += src[33];

        // reduce row sums across the 4 lanes of each quad
#pragma unroll
        for (int off = 1; off <= 2; off <<= 1) {
            lsum0 += __shfl_xor_sync(0xffffffffu, lsum0, off);
            lsum1 += __shfl_xor_sync(0xffffffffu, lsum1, off);
        }
        const float inv0 = 1.0f / lsum0, inv1 = 1.0f / lsum1;

        const int g = lane >> 2, tq = lane & 3;
        const int r0 = q0 + qw * 16 + g, r1 = r0 + 8;
#pragma unroll
        for (int df = 0; df < 8; df++) {
            const int col = df * 8 + 2 * tq;
            uint32_t h01, l01;
            fsplit2(oacc[df][0] * inv0, oacc[df][1] * inv0, h01, l01);
            *(uint32_t*)(ahi + (size_t)r0 * D + h * HD + col) = h01;
            *(uint32_t*)(alo + (size_t)r0 * D + h * HD + col) = l01;
            fsplit2(oacc[df][2] * inv1, oacc[df][3] * inv1, h01, l01);
            *(uint32_t*)(ahi + (size_t)r1 * D + h * HD + col) = h01;
            *(uint32_t*)(alo + (size_t)r1 * D + h * HD + col) = l01;
        }
    }
}

// ---------------------------------------------------------------------------
extern "C" void kernel_launch(void* const* d_in, const int* in_sizes, int n_in,
                              void* d_out, int out_size) {
    const float* ut  = (const float*)d_in[0];
    const float* rc  = (const float*)d_in[1];
    const float* mem = (const float*)d_in[2];
    const float* lck = (const float*)d_in[3];
    const float* lcv = (const float*)d_in[4];
    const float* Wq  = (const float*)d_in[5];
    const float* bq  = (const float*)d_in[6];
    const float* Wkv = (const float*)d_in[7];
    const float* bkv = (const float*)d_in[8];
    const float* Wo  = (const float*)d_in[9];
    const float* bo  = (const float*)d_in[10];

    float* out  = (float*)d_out;
    float* keyb = out + KEY_OFF;
    float* valb = out + VAL_OFF;

    __nv_bfloat16 *qih, *qil, *kvh, *kvl, *wqh, *wql, *wkh, *wkl, *woh, *wol;
    __nv_bfloat16 *ath, *atl;
    __half *qf, *kf, *vf;
    cudaGetSymbolAddress((void**)&qih, g_qin_hi);  cudaGetSymbolAddress((void**)&qil, g_qin_lo);
    cudaGetSymbolAddress((void**)&kvh, g_kvin_hi); cudaGetSymbolAddress((void**)&kvl, g_kvin_lo);
    cudaGetSymbolAddress((void**)&wqh, g_wq_hi);   cudaGetSymbolAddress((void**)&wql, g_wq_lo);
    cudaGetSymbolAddress((void**)&wkh, g_wkv_hi);  cudaGetSymbolAddress((void**)&wkl, g_wkv_lo);
    cudaGetSymbolAddress((void**)&woh, g_wo_hi);   cudaGetSymbolAddress((void**)&wol, g_wo_lo);
    cudaGetSymbolAddress((void**)&qf, g_q_f16);    cudaGetSymbolAddress((void**)&kf, g_k_f16);
    cudaGetSymbolAddress((void**)&vf, g_v_f16);
    cudaGetSymbolAddress((void**)&ath, g_at_hi);   cudaGetSymbolAddress((void**)&atl, g_at_lo);

    cudaFuncSetAttribute(gemm_mma, cudaFuncAttributeMaxDynamicSharedMemorySize, GEMM_SMEM);
    cudaFuncSetAttribute(attn_mma, cudaFuncAttributeMaxDynamicSharedMemorySize, ATT_SMEM);

    // launch 0: weights
    conv_w<<<dim3(2048, 3), 256>>>(Wq, Wkv, Wo, wqh, wql, wkh, wkl, woh, wol);
    // launch 1: activations
    conv_act<<<dim3(2048, 5), 256>>>(rc, ut, mem, qih, qil, kvh, kvl);
    // launch 2: left-context
    conv_lc<<<(L_LEN * D) / 256, 256>>>(lck, lcv, keyb, valb, kf, vf);

    // launch 3: q = (q_in @ Wq^T + bq) * 0.125*log2e -> fp16
    gemm_mma<<<dim3(D / 128, QLEN / 128), 512, GEMM_SMEM>>>(
        qih, qil, wqh, wql, bq, D, D, 1,
        nullptr, nullptr, qf, nullptr);
    // launch 4: kv = kv_in @ Wkv^T + bkv -> key/value fp32 (+L-shift) + k/v fp16
    gemm_mma<<<dim3(2 * D / 128, KVIN / 128), 512, GEMM_SMEM>>>(
        kvh, kvl, wkh, wkl, bkv, D, 2 * D, 2,
        keyb, valb, kf, vf);
    // launch 5 (ncu -s 5 target): attention -> attn bf16 hi/lo
    attn_mma<<<dim3(QLEN / 128, NH), 512, ATT_SMEM>>>(
        qf, kf, vf, ath, atl);
    // launch 6: out = attn @ Wo^T + bo
    gemm_mma<<<dim3(D / 128, QLEN / 128), 512, GEMM_SMEM>>>(
        ath, atl, woh, wol, bo, D, D, 0,
        out, nullptr, nullptr, nullptr);
}